// round 5
// baseline (speedup 1.0000x reference)
#include <cuda_runtime.h>
#include <math.h>

// Problem constants (fixed bench shapes)
#define BB    128
#define NN    1024
#define DIN   192
#define HH    128
#define KSLOT 3
#define NITER 3
#define EPSX  1e-5f
#define MTOT  (BB*NN)              // 131072 token rows
#define SCALE 0.08838834764831845f // 1/sqrt(128)

// ---------------------------------------------------------------------------
// Scratch (device globals: allocation-free rule)
// ---------------------------------------------------------------------------
__device__ float g_WpT[DIN*HH];
__device__ float g_WkT[HH*HH];
__device__ float g_WvT[HH*HH];
__device__ float g_inputs[(size_t)MTOT*HH];  // 67 MB
__device__ float g_k[(size_t)MTOT*HH];       // 67 MB
__device__ float g_v[(size_t)MTOT*HH];       // 67 MB
__device__ float g_slots[BB*KSLOT*HH];

// ---------------------------------------------------------------------------
// Prep: transpose weights for coalesced GEMM B-loads; init slots
// ---------------------------------------------------------------------------
__global__ void prep_kernel(const float* __restrict__ Wp,
                            const float* __restrict__ Wk,
                            const float* __restrict__ Wv,
                            const float* __restrict__ noise,
                            const float* __restrict__ slot_mu,
                            const float* __restrict__ slot_lsig)
{
    int i = blockIdx.x * blockDim.x + threadIdx.x;
    if (i < HH*DIN) {                 // Wp: [128][192] -> WpT[192][128]
        int r = i / DIN, c = i % DIN;
        g_WpT[c*HH + r] = Wp[i];
    }
    if (i < HH*HH) {                  // Wk, Wv: [128][128] -> transposed
        int r = i >> 7, c = i & 127;
        g_WkT[c*HH + r] = Wk[i];
        g_WvT[c*HH + r] = Wv[i];
    }
    if (i < BB*KSLOT*HH) {            // slots = mu + exp(log_sigma)*noise
        int kh = i % (KSLOT*HH);
        g_slots[i] = slot_mu[kh] + expf(slot_lsig[kh]) * noise[i];
    }
}

// ---------------------------------------------------------------------------
// SGEMM: C[128 x 128] tile per block, 256 threads, 8x8 register tiles.
// out[m, j] = sum_i A[m,i] * Bm[i,j] + bias[j], optional row LayerNorm.
// Bm is the transposed weight (KDIM x 128), row-major, coalesced.
// ---------------------------------------------------------------------------
template<int KDIM, bool DO_LN>
__global__ void __launch_bounds__(256)
gemm128(const float* __restrict__ A, const float* __restrict__ Bm,
        const float* __restrict__ bias, const float* __restrict__ gamma,
        const float* __restrict__ beta, float* __restrict__ out)
{
    __shared__ __align__(16) float As[8][132];   // [k][m], padded
    __shared__ __align__(16) float Bs[8][128];   // [k][n]
    __shared__ float psum[16][129];
    __shared__ float psq [16][129];
    __shared__ float smu[128], srs[128];

    const int tid = threadIdx.x;
    const int tx = tid & 15, ty = tid >> 4;
    const int m0 = blockIdx.x * 128;

    const int aRow = tid >> 1;          // 0..127
    const int aCol = (tid & 1) * 4;     // 0 or 4
    const int bRow = tid >> 5;          // 0..7
    const int bCol = (tid & 31) * 4;    // 0..124

    const float* Ab = A + (size_t)m0 * KDIM;

    float acc[8][8];
    #pragma unroll
    for (int i = 0; i < 8; i++)
        #pragma unroll
        for (int j = 0; j < 8; j++) acc[i][j] = 0.f;

    for (int kt = 0; kt < KDIM; kt += 8) {
        float4 a4 = *(const float4*)(Ab + (size_t)aRow * KDIM + (kt + aCol));
        As[aCol+0][aRow] = a4.x;
        As[aCol+1][aRow] = a4.y;
        As[aCol+2][aRow] = a4.z;
        As[aCol+3][aRow] = a4.w;
        *(float4*)&Bs[bRow][bCol] =
            *(const float4*)(Bm + (size_t)(kt + bRow) * HH + bCol);
        __syncthreads();
        #pragma unroll
        for (int kk = 0; kk < 8; kk++) {
            float a[8], bf[8];
            *(float4*)&a[0]  = *(const float4*)&As[kk][ty*8];
            *(float4*)&a[4]  = *(const float4*)&As[kk][ty*8+4];
            *(float4*)&bf[0] = *(const float4*)&Bs[kk][tx*8];
            *(float4*)&bf[4] = *(const float4*)&Bs[kk][tx*8+4];
            #pragma unroll
            for (int i = 0; i < 8; i++)
                #pragma unroll
                for (int j = 0; j < 8; j++)
                    acc[i][j] = fmaf(a[i], bf[j], acc[i][j]);
        }
        __syncthreads();
    }

    float bj[8];
    #pragma unroll
    for (int j = 0; j < 8; j++) bj[j] = bias[tx*8 + j];
    #pragma unroll
    for (int i = 0; i < 8; i++)
        #pragma unroll
        for (int j = 0; j < 8; j++) acc[i][j] += bj[j];

    if (DO_LN) {
        #pragma unroll
        for (int i = 0; i < 8; i++) {
            int row = ty*8 + i;
            float s = 0.f, q = 0.f;
            #pragma unroll
            for (int j = 0; j < 8; j++) { s += acc[i][j]; q += acc[i][j]*acc[i][j]; }
            psum[tx][row] = s;
            psq [tx][row] = q;
        }
        __syncthreads();
        if (tid < 128) {
            float s = 0.f, q = 0.f;
            #pragma unroll
            for (int t = 0; t < 16; t++) { s += psum[t][tid]; q += psq[t][tid]; }
            float mu  = s * (1.f/128.f);
            float var = q * (1.f/128.f) - mu*mu;
            smu[tid] = mu;
            srs[tid] = rsqrtf(var + EPSX);
        }
        __syncthreads();
        float gj[8], b2j[8];
        #pragma unroll
        for (int j = 0; j < 8; j++) { gj[j] = gamma[tx*8+j]; b2j[j] = beta[tx*8+j]; }
        #pragma unroll
        for (int i = 0; i < 8; i++) {
            int row = ty*8 + i;
            float mu = smu[row], rs = srs[row];
            float o[8];
            #pragma unroll
            for (int j = 0; j < 8; j++) o[j] = (acc[i][j]-mu)*rs*gj[j] + b2j[j];
            float4* dst = (float4*)(out + (size_t)(m0+row)*HH + tx*8);
            dst[0] = make_float4(o[0], o[1], o[2], o[3]);
            dst[1] = make_float4(o[4], o[5], o[6], o[7]);
        }
    } else {
        #pragma unroll
        for (int i = 0; i < 8; i++) {
            int row = ty*8 + i;
            float4* dst = (float4*)(out + (size_t)(m0+row)*HH + tx*8);
            dst[0] = make_float4(acc[i][0], acc[i][1], acc[i][2], acc[i][3]);
            dst[1] = make_float4(acc[i][4], acc[i][5], acc[i][6], acc[i][7]);
        }
    }
}

// ---------------------------------------------------------------------------
// Fused per-iteration kernel: one block per batch element.
// LN(slots) -> q -> attention (softmax over 3 slots) -> updates -> GRU -> MLP
// ---------------------------------------------------------------------------
__device__ __forceinline__ float geluf(float x) {
    return 0.5f * x * (1.f + erff(x * 0.70710678118654752f));
}

__device__ __forceinline__ void warp_ln_row(const float* __restrict__ src,
                                            float* __restrict__ dst,
                                            const float* __restrict__ gamma,
                                            const float* __restrict__ beta,
                                            int lane)
{
    float4 xv = *(const float4*)(src + lane*4);
    float s = xv.x + xv.y + xv.z + xv.w;
    #pragma unroll
    for (int off = 16; off > 0; off >>= 1) s += __shfl_xor_sync(0xffffffffu, s, off);
    float mu = s * (1.f/128.f);
    float d0 = xv.x-mu, d1 = xv.y-mu, d2 = xv.z-mu, d3 = xv.w-mu;
    float q = d0*d0 + d1*d1 + d2*d2 + d3*d3;
    #pragma unroll
    for (int off = 16; off > 0; off >>= 1) q += __shfl_xor_sync(0xffffffffu, q, off);
    float rs = rsqrtf(q * (1.f/128.f) + EPSX);
    float4 g4 = *(const float4*)(gamma + lane*4);
    float4 b4 = *(const float4*)(beta  + lane*4);
    float4 o;
    o.x = d0*rs*g4.x + b4.x;
    o.y = d1*rs*g4.y + b4.y;
    o.z = d2*rs*g4.z + b4.z;
    o.w = d3*rs*g4.w + b4.w;
    *(float4*)(dst + lane*4) = o;
}

__global__ void __launch_bounds__(512)
iter_kernel(const float* __restrict__ Wq,  const float* __restrict__ bq,
            const float* __restrict__ gs,  const float* __restrict__ bs,
            const float* __restrict__ Wih, const float* __restrict__ bih,
            const float* __restrict__ Whh, const float* __restrict__ bhh,
            const float* __restrict__ W1,  const float* __restrict__ b1,
            const float* __restrict__ W2,  const float* __restrict__ b2,
            const float* __restrict__ gm,  const float* __restrict__ bm,
            float* __restrict__ out_slots, float* __restrict__ out_attn,
            int writeSlots, int writeAttn)
{
    __shared__ __align__(16) float s_prev[KSLOT][HH];
    __shared__ __align__(16) float s_ln  [KSLOT][HH];
    __shared__ __align__(16) float q_s   [KSLOT][HH];
    __shared__ __align__(16) float uacc  [16][KSLOT][HH];   // per-warp update accs
    __shared__ __align__(16) float u_s   [KSLOT][HH];
    __shared__ __align__(16) float gi_s  [KSLOT][3*HH];
    __shared__ __align__(16) float gh_s  [KSLOT][3*HH];
    __shared__ __align__(16) float s_new [KSLOT][HH];
    __shared__ __align__(16) float m_ln  [KSLOT][HH];
    __shared__ __align__(16) float h1_s  [KSLOT][2*HH];

    const int b    = blockIdx.x;
    const int tid  = threadIdx.x;
    const int lane = tid & 31;
    const int warp = tid >> 5;

    if (tid < KSLOT*HH) s_prev[0][tid] = g_slots[b*KSLOT*HH + tid];
    __syncthreads();

    // --- LN(slots) with g_s/b_s ---
    if (warp < KSLOT) warp_ln_row(s_prev[warp], s_ln[warp], gs, bs, lane);
    __syncthreads();

    // --- q = s_ln @ Wq^T + bq, scale folded in ---
    if (tid < HH) {
        const int j = tid;
        const float4* wr = (const float4*)(Wq + (size_t)j*HH);
        float d0 = 0.f, d1 = 0.f, d2 = 0.f;
        #pragma unroll 8
        for (int i = 0; i < HH/4; i++) {
            float4 w  = wr[i];
            float4 a0 = *(const float4*)&s_ln[0][i*4];
            float4 a1 = *(const float4*)&s_ln[1][i*4];
            float4 a2 = *(const float4*)&s_ln[2][i*4];
            d0 += w.x*a0.x + w.y*a0.y + w.z*a0.z + w.w*a0.w;
            d1 += w.x*a1.x + w.y*a1.y + w.z*a1.z + w.w*a1.w;
            d2 += w.x*a2.x + w.y*a2.y + w.z*a2.z + w.w*a2.w;
        }
        float bb = bq[j];
        q_s[0][j] = (d0 + bb) * SCALE;
        q_s[1][j] = (d1 + bb) * SCALE;
        q_s[2][j] = (d2 + bb) * SCALE;
    }
    __syncthreads();

    // --- attention: warp-per-token, softmax over the 3 slots ---
    float4 q0 = *(const float4*)&q_s[0][lane*4];
    float4 q1 = *(const float4*)&q_s[1][lane*4];
    float4 q2 = *(const float4*)&q_s[2][lane*4];
    float a00=0,a01=0,a02=0,a03=0;
    float a10=0,a11=0,a12=0,a13=0;
    float a20=0,a21=0,a22=0,a23=0;
    const float* kb = g_k + (size_t)b*NN*HH;
    const float* vb = g_v + (size_t)b*NN*HH;
    #pragma unroll 2
    for (int n = warp; n < NN; n += 16) {
        float4 kv = *(const float4*)(kb + (size_t)n*HH + lane*4);
        float d0 = q0.x*kv.x + q0.y*kv.y + q0.z*kv.z + q0.w*kv.w;
        float d1 = q1.x*kv.x + q1.y*kv.y + q1.z*kv.z + q1.w*kv.w;
        float d2 = q2.x*kv.x + q2.y*kv.y + q2.z*kv.z + q2.w*kv.w;
        #pragma unroll
        for (int off = 16; off > 0; off >>= 1) {
            d0 += __shfl_xor_sync(0xffffffffu, d0, off);
            d1 += __shfl_xor_sync(0xffffffffu, d1, off);
            d2 += __shfl_xor_sync(0xffffffffu, d2, off);
        }
        float mx = fmaxf(d0, fmaxf(d1, d2));
        float e0 = expf(d0-mx), e1 = expf(d1-mx), e2 = expf(d2-mx);
        float inv = 1.f / (e0 + e1 + e2);
        float w0 = e0*inv, w1 = e1*inv, w2 = e2*inv;
        if (writeAttn && lane < 3) {
            float wv = (lane == 0) ? w0 : (lane == 1) ? w1 : w2;
            out_attn[((size_t)b*KSLOT + lane)*NN + n] = wv;
        }
        float4 vv = *(const float4*)(vb + (size_t)n*HH + lane*4);
        a00 += w0*vv.x; a01 += w0*vv.y; a02 += w0*vv.z; a03 += w0*vv.w;
        a10 += w1*vv.x; a11 += w1*vv.y; a12 += w1*vv.z; a13 += w1*vv.w;
        a20 += w2*vv.x; a21 += w2*vv.y; a22 += w2*vv.z; a23 += w2*vv.w;
    }
    *(float4*)&uacc[warp][0][lane*4] = make_float4(a00,a01,a02,a03);
    *(float4*)&uacc[warp][1][lane*4] = make_float4(a10,a11,a12,a13);
    *(float4*)&uacc[warp][2][lane*4] = make_float4(a20,a21,a22,a23);
    __syncthreads();
    if (tid < KSLOT*HH) {
        int s = tid >> 7, j = tid & 127;
        float acc = 0.f;
        #pragma unroll
        for (int w = 0; w < 16; w++) acc += uacc[w][s][j];
        u_s[s][j] = acc;
    }
    __syncthreads();

    // --- GRU gates: gi = u @ Wih^T + bih ; gh = h @ Whh^T + bhh ---
    if (tid < 3*HH) {
        const int o = tid;
        {
            const float4* wr = (const float4*)(Wih + (size_t)o*HH);
            float d0=0,d1=0,d2=0;
            #pragma unroll 4
            for (int i = 0; i < HH/4; i++) {
                float4 w  = wr[i];
                float4 a0 = *(const float4*)&u_s[0][i*4];
                float4 a1 = *(const float4*)&u_s[1][i*4];
                float4 a2 = *(const float4*)&u_s[2][i*4];
                d0 += w.x*a0.x + w.y*a0.y + w.z*a0.z + w.w*a0.w;
                d1 += w.x*a1.x + w.y*a1.y + w.z*a1.z + w.w*a1.w;
                d2 += w.x*a2.x + w.y*a2.y + w.z*a2.z + w.w*a2.w;
            }
            float bb = bih[o];
            gi_s[0][o] = d0+bb; gi_s[1][o] = d1+bb; gi_s[2][o] = d2+bb;
        }
        {
            const float4* wr = (const float4*)(Whh + (size_t)o*HH);
            float d0=0,d1=0,d2=0;
            #pragma unroll 4
            for (int i = 0; i < HH/4; i++) {
                float4 w  = wr[i];
                float4 a0 = *(const float4*)&s_prev[0][i*4];
                float4 a1 = *(const float4*)&s_prev[1][i*4];
                float4 a2 = *(const float4*)&s_prev[2][i*4];
                d0 += w.x*a0.x + w.y*a0.y + w.z*a0.z + w.w*a0.w;
                d1 += w.x*a1.x + w.y*a1.y + w.z*a1.z + w.w*a1.w;
                d2 += w.x*a2.x + w.y*a2.y + w.z*a2.z + w.w*a2.w;
            }
            float bb = bhh[o];
            gh_s[0][o] = d0+bb; gh_s[1][o] = d1+bb; gh_s[2][o] = d2+bb;
        }
    }
    __syncthreads();
    if (tid < KSLOT*HH) {
        int s = tid >> 7, j = tid & 127;
        float ir = gi_s[s][j], iz = gi_s[s][HH+j], inn = gi_s[s][2*HH+j];
        float hr = gh_s[s][j], hz = gh_s[s][HH+j], hn  = gh_s[s][2*HH+j];
        float r  = 1.f / (1.f + expf(-(ir+hr)));
        float z  = 1.f / (1.f + expf(-(iz+hz)));
        float nn = tanhf(inn + r*hn);
        s_new[s][j] = (1.f - z)*nn + z*s_prev[s][j];
    }
    __syncthreads();

    // --- MLP with residual ---
    if (warp < KSLOT) warp_ln_row(s_new[warp], m_ln[warp], gm, bm, lane);
    __syncthreads();
    if (tid < 2*HH) {
        const int jr = tid;
        const float4* wr = (const float4*)(W1 + (size_t)jr*HH);
        float d0=0,d1=0,d2=0;
        #pragma unroll 4
        for (int i = 0; i < HH/4; i++) {
            float4 w  = wr[i];
            float4 a0 = *(const float4*)&m_ln[0][i*4];
            float4 a1 = *(const float4*)&m_ln[1][i*4];
            float4 a2 = *(const float4*)&m_ln[2][i*4];
            d0 += w.x*a0.x + w.y*a0.y + w.z*a0.z + w.w*a0.w;
            d1 += w.x*a1.x + w.y*a1.y + w.z*a1.z + w.w*a1.w;
            d2 += w.x*a2.x + w.y*a2.y + w.z*a2.z + w.w*a2.w;
        }
        float bb = b1[jr];
        h1_s[0][jr] = geluf(d0+bb);
        h1_s[1][jr] = geluf(d1+bb);
        h1_s[2][jr] = geluf(d2+bb);
    }
    __syncthreads();
    if (tid < HH) {
        const int j = tid;
        const float4* wr = (const float4*)(W2 + (size_t)j*2*HH);
        float d0=0,d1=0,d2=0;
        #pragma unroll 4
        for (int i = 0; i < (2*HH)/4; i++) {
            float4 w  = wr[i];
            float4 a0 = *(const float4*)&h1_s[0][i*4];
            float4 a1 = *(const float4*)&h1_s[1][i*4];
            float4 a2 = *(const float4*)&h1_s[2][i*4];
            d0 += w.x*a0.x + w.y*a0.y + w.z*a0.z + w.w*a0.w;
            d1 += w.x*a1.x + w.y*a1.y + w.z*a1.z + w.w*a1.w;
            d2 += w.x*a2.x + w.y*a2.y + w.z*a2.z + w.w*a2.w;
        }
        float bb = b2[j];
        float f0 = s_new[0][j] + d0 + bb;
        float f1 = s_new[1][j] + d1 + bb;
        float f2 = s_new[2][j] + d2 + bb;
        g_slots[b*KSLOT*HH + 0*HH + j] = f0;
        g_slots[b*KSLOT*HH + 1*HH + j] = f1;
        g_slots[b*KSLOT*HH + 2*HH + j] = f2;
        if (writeSlots) {
            out_slots[(size_t)b*KSLOT*HH + 0*HH + j] = f0;
            out_slots[(size_t)b*KSLOT*HH + 1*HH + j] = f1;
            out_slots[(size_t)b*KSLOT*HH + 2*HH + j] = f2;
        }
    }
}

// ---------------------------------------------------------------------------
// Launch
// ---------------------------------------------------------------------------
extern "C" void kernel_launch(void* const* d_in, const int* in_sizes, int n_in,
                              void* d_out, int out_size)
{
    const float* patch = (const float*)d_in[0];
    const float* noise = (const float*)d_in[1];
    const float* smu   = (const float*)d_in[2];
    const float* slsig = (const float*)d_in[3];
    const float* Wp    = (const float*)d_in[4];
    const float* bp    = (const float*)d_in[5];
    const float* g_in  = (const float*)d_in[6];
    const float* b_in  = (const float*)d_in[7];
    const float* Wq    = (const float*)d_in[8];
    const float* bq    = (const float*)d_in[9];
    const float* Wk    = (const float*)d_in[10];
    const float* bk    = (const float*)d_in[11];
    const float* Wv    = (const float*)d_in[12];
    const float* bv    = (const float*)d_in[13];
    const float* Wih   = (const float*)d_in[14];
    const float* bih   = (const float*)d_in[15];
    const float* Whh   = (const float*)d_in[16];
    const float* bhh   = (const float*)d_in[17];
    const float* gs    = (const float*)d_in[18];
    const float* bs    = (const float*)d_in[19];
    const float* W1    = (const float*)d_in[20];
    const float* b1    = (const float*)d_in[21];
    const float* W2    = (const float*)d_in[22];
    const float* b2    = (const float*)d_in[23];
    const float* gm    = (const float*)d_in[24];
    const float* bm    = (const float*)d_in[25];

    float *pWpT, *pWkT, *pWvT, *pIn, *pK, *pV;
    cudaGetSymbolAddress((void**)&pWpT, g_WpT);
    cudaGetSymbolAddress((void**)&pWkT, g_WkT);
    cudaGetSymbolAddress((void**)&pWvT, g_WvT);
    cudaGetSymbolAddress((void**)&pIn,  g_inputs);
    cudaGetSymbolAddress((void**)&pK,   g_k);
    cudaGetSymbolAddress((void**)&pV,   g_v);

    const int slotsElems = BB*KSLOT*HH;                 // 49152
    const int attnElems  = BB*KSLOT*NN;                 // 393216
    const int writeSlots = (out_size >= slotsElems) ? 1 : 0;
    const int writeAttn  = (out_size >= slotsElems + attnElems) ? 1 : 0;
    float* outSlots = (float*)d_out;
    float* outAttn  = (float*)d_out + slotsElems;

    // 1) transpose weights + init slots
    prep_kernel<<<192, 256>>>(Wp, Wk, Wv, noise, smu, slsig);

    // 2) inputs = LN(X @ Wp^T + bp)
    gemm128<DIN, true><<<MTOT/128, 256>>>(patch, pWpT, bp, g_in, b_in, pIn);

    // 3) k, v projections
    gemm128<HH, false><<<MTOT/128, 256>>>(pIn, pWkT, bk, nullptr, nullptr, pK);
    gemm128<HH, false><<<MTOT/128, 256>>>(pIn, pWvT, bv, nullptr, nullptr, pV);

    // 4) 3 slot-attention iterations (fused)
    for (int it = 0; it < NITER; it++) {
        int last = (it == NITER - 1);
        iter_kernel<<<BB, 512>>>(Wq, bq, gs, bs, Wih, bih, Whh, bhh,
                                 W1, b1, W2, b2, gm, bm,
                                 outSlots, outAttn,
                                 last ? writeSlots : 0,
                                 last ? writeAttn  : 0);
    }
}

// round 6
// speedup vs baseline: 1.1262x; 1.1262x over previous
#include <cuda_runtime.h>
#include <math.h>

// Problem constants (fixed bench shapes)
#define BB    128
#define NN    1024
#define DIN   192
#define HH    128
#define KSLOT 3
#define NITER 3
#define EPSX  1e-5f
#define MTOT  (BB*NN)              // 131072 token rows
#define SCALE 0.08838834764831845f // 1/sqrt(128)

typedef unsigned long long ull;

// ---------------------------------------------------------------------------
// Scratch (device globals: allocation-free rule)
// ---------------------------------------------------------------------------
__device__ float g_WpT[DIN*HH];
__device__ float g_WkT[HH*HH];
__device__ float g_WvT[HH*HH];
__device__ float g_inputs[(size_t)MTOT*HH];  // 67 MB
__device__ float g_kT[(size_t)MTOT*HH];      // 67 MB, layout [B][H][N]
__device__ float g_v[(size_t)MTOT*HH];       // 67 MB, layout [B][N][H]
__device__ float g_slots[BB*KSLOT*HH];

// f32x2 helpers ------------------------------------------------------------
__device__ __forceinline__ ull splat2(float a) {
    ull r; asm("mov.b64 %0, {%1, %1};" : "=l"(r) : "f"(a)); return r;
}
__device__ __forceinline__ void fma2(ull& d, ull a, ull b) {
    asm("fma.rn.f32x2 %0, %1, %2, %0;" : "+l"(d) : "l"(a), "l"(b));
}
__device__ __forceinline__ float2 unpack2(ull v) {
    float2 r; asm("mov.b64 {%0, %1}, %2;" : "=f"(r.x), "=f"(r.y) : "l"(v)); return r;
}

// ---------------------------------------------------------------------------
// Prep: transpose weights; init slots
// ---------------------------------------------------------------------------
__global__ void prep_kernel(const float* __restrict__ Wp,
                            const float* __restrict__ Wk,
                            const float* __restrict__ Wv,
                            const float* __restrict__ noise,
                            const float* __restrict__ slot_mu,
                            const float* __restrict__ slot_lsig)
{
    int i = blockIdx.x * blockDim.x + threadIdx.x;
    if (i < HH*DIN) {                 // Wp: [128][192] -> WpT[192][128]
        int r = i / DIN, c = i % DIN;
        g_WpT[c*HH + r] = Wp[i];
    }
    if (i < HH*HH) {                  // Wk, Wv transposed
        int r = i >> 7, c = i & 127;
        g_WkT[c*HH + r] = Wk[i];
        g_WvT[c*HH + r] = Wv[i];
    }
    if (i < BB*KSLOT*HH) {
        int kh = i % (KSLOT*HH);
        g_slots[i] = slot_mu[kh] + expf(slot_lsig[kh]) * noise[i];
    }
}

// ---------------------------------------------------------------------------
// SGEMM with packed f32x2 FMA. 128x128 tile / block, 256 threads, 8x8 tile
// (stored as 8x4 f32x2 accumulators).
// TRANS_OUT=1: write output transposed as [b][feature][n] (for kT).
// ---------------------------------------------------------------------------
template<int KDIM, bool DO_LN, bool TRANS_OUT>
__global__ void __launch_bounds__(256)
gemm128(const float* __restrict__ A, const float* __restrict__ Bm,
        const float* __restrict__ bias, const float* __restrict__ gamma,
        const float* __restrict__ beta, float* __restrict__ out)
{
    __shared__ __align__(16) float As[8][132];   // [k][m]
    __shared__ __align__(16) float Bs[8][128];   // [k][n]
    __shared__ float psum[16][129];
    __shared__ float psq [16][129];
    __shared__ float smu[128], srs[128];

    const int tid = threadIdx.x;
    const int tx = tid & 15, ty = tid >> 4;
    const int m0 = blockIdx.x * 128;

    const int aRow = tid >> 1;
    const int aCol = (tid & 1) * 4;
    const int bRow = tid >> 5;
    const int bCol = (tid & 31) * 4;

    const float* Ab = A + (size_t)m0 * KDIM;

    ull acc2[8][4];
    #pragma unroll
    for (int i = 0; i < 8; i++)
        #pragma unroll
        for (int j = 0; j < 4; j++) acc2[i][j] = 0ull;

    for (int kt = 0; kt < KDIM; kt += 8) {
        float4 a4 = *(const float4*)(Ab + (size_t)aRow * KDIM + (kt + aCol));
        As[aCol+0][aRow] = a4.x;
        As[aCol+1][aRow] = a4.y;
        As[aCol+2][aRow] = a4.z;
        As[aCol+3][aRow] = a4.w;
        *(float4*)&Bs[bRow][bCol] =
            *(const float4*)(Bm + (size_t)(kt + bRow) * HH + bCol);
        __syncthreads();
        #pragma unroll
        for (int kk = 0; kk < 8; kk++) {
            float a[8];
            *(float4*)&a[0] = *(const float4*)&As[kk][ty*8];
            *(float4*)&a[4] = *(const float4*)&As[kk][ty*8+4];
            ull b2[4];
            const ull* bp = (const ull*)&Bs[kk][tx*8];
            b2[0] = bp[0]; b2[1] = bp[1]; b2[2] = bp[2]; b2[3] = bp[3];
            #pragma unroll
            for (int i = 0; i < 8; i++) {
                ull av = splat2(a[i]);
                fma2(acc2[i][0], av, b2[0]);
                fma2(acc2[i][1], av, b2[1]);
                fma2(acc2[i][2], av, b2[2]);
                fma2(acc2[i][3], av, b2[3]);
            }
        }
        __syncthreads();
    }

    // unpack + bias
    float accf[8][8];
    float bj[8];
    #pragma unroll
    for (int j = 0; j < 8; j++) bj[j] = bias[tx*8 + j];
    #pragma unroll
    for (int i = 0; i < 8; i++)
        #pragma unroll
        for (int jp = 0; jp < 4; jp++) {
            float2 f = unpack2(acc2[i][jp]);
            accf[i][2*jp]   = f.x + bj[2*jp];
            accf[i][2*jp+1] = f.y + bj[2*jp+1];
        }

    if (DO_LN) {
        #pragma unroll
        for (int i = 0; i < 8; i++) {
            int row = ty*8 + i;
            float s = 0.f, q = 0.f;
            #pragma unroll
            for (int j = 0; j < 8; j++) { s += accf[i][j]; q += accf[i][j]*accf[i][j]; }
            psum[tx][row] = s;
            psq [tx][row] = q;
        }
        __syncthreads();
        if (tid < 128) {
            float s = 0.f, q = 0.f;
            #pragma unroll
            for (int t = 0; t < 16; t++) { s += psum[t][tid]; q += psq[t][tid]; }
            float mu  = s * (1.f/128.f);
            float var = q * (1.f/128.f) - mu*mu;
            smu[tid] = mu;
            srs[tid] = rsqrtf(var + EPSX);
        }
        __syncthreads();
        float gj[8], b2j[8];
        #pragma unroll
        for (int j = 0; j < 8; j++) { gj[j] = gamma[tx*8+j]; b2j[j] = beta[tx*8+j]; }
        #pragma unroll
        for (int i = 0; i < 8; i++) {
            int row = ty*8 + i;
            float mu = smu[row], rs = srs[row];
            float o[8];
            #pragma unroll
            for (int j = 0; j < 8; j++) o[j] = (accf[i][j]-mu)*rs*gj[j] + b2j[j];
            float4* dst = (float4*)(out + (size_t)(m0+row)*HH + tx*8);
            dst[0] = make_float4(o[0], o[1], o[2], o[3]);
            dst[1] = make_float4(o[4], o[5], o[6], o[7]);
        }
    } else if (TRANS_OUT) {
        // out layout [b][feature][n]; all 128 rows of this block share one b
        const int bidx = m0 >> 10, n0 = m0 & 1023;
        float* Ob = out + (size_t)bidx * HH * NN + n0;
        #pragma unroll
        for (int j = 0; j < 8; j++) {
            int feat = tx*8 + j;
            float* row = Ob + (size_t)feat * NN + ty*8;
            *(float4*)(row)     = make_float4(accf[0][j], accf[1][j], accf[2][j], accf[3][j]);
            *(float4*)(row + 4) = make_float4(accf[4][j], accf[5][j], accf[6][j], accf[7][j]);
        }
    } else {
        #pragma unroll
        for (int i = 0; i < 8; i++) {
            int row = ty*8 + i;
            float4* dst = (float4*)(out + (size_t)(m0+row)*HH + tx*8);
            dst[0] = make_float4(accf[i][0], accf[i][1], accf[i][2], accf[i][3]);
            dst[1] = make_float4(accf[i][4], accf[i][5], accf[i][6], accf[i][7]);
        }
    }
}

// ---------------------------------------------------------------------------
// Fused per-iteration kernel: one block per batch element, 512 threads.
// Phase A: thread-per-2-tokens dot products from kT (no shuffles), softmax
//          over 3 slots (thread-local), weights to shared.
// Phase B: warp-per-token-strip w@v accumulation.
// Then GRU + MLP as small shared-memory GEMVs.
// ---------------------------------------------------------------------------
__device__ __forceinline__ float geluf(float x) {
    return 0.5f * x * (1.f + erff(x * 0.70710678118654752f));
}

__device__ __forceinline__ void warp_ln_row(const float* __restrict__ src,
                                            float* __restrict__ dst,
                                            const float* __restrict__ gamma,
                                            const float* __restrict__ beta,
                                            int lane)
{
    float4 xv = *(const float4*)(src + lane*4);
    float s = xv.x + xv.y + xv.z + xv.w;
    #pragma unroll
    for (int off = 16; off > 0; off >>= 1) s += __shfl_xor_sync(0xffffffffu, s, off);
    float mu = s * (1.f/128.f);
    float d0 = xv.x-mu, d1 = xv.y-mu, d2 = xv.z-mu, d3 = xv.w-mu;
    float q = d0*d0 + d1*d1 + d2*d2 + d3*d3;
    #pragma unroll
    for (int off = 16; off > 0; off >>= 1) q += __shfl_xor_sync(0xffffffffu, q, off);
    float rs = rsqrtf(q * (1.f/128.f) + EPSX);
    float4 g4 = *(const float4*)(gamma + lane*4);
    float4 b4 = *(const float4*)(beta  + lane*4);
    float4 o;
    o.x = d0*rs*g4.x + b4.x;
    o.y = d1*rs*g4.y + b4.y;
    o.z = d2*rs*g4.z + b4.z;
    o.w = d3*rs*g4.w + b4.w;
    *(float4*)(dst + lane*4) = o;
}

struct SmemAttn {
    float w[KSLOT][NN];          // 12 KB
    float uacc[16][KSLOT][HH];   // 24 KB
};
struct SmemGru {
    float gi[KSLOT][3*HH];       // 4.5 KB
    float gh[KSLOT][3*HH];       // 4.5 KB
    float h1[KSLOT][2*HH];       // 3 KB
};
union SmemUnion { SmemAttn a; SmemGru g; };

__global__ void __launch_bounds__(512)
iter_kernel(const float* __restrict__ Wq,  const float* __restrict__ bq,
            const float* __restrict__ gs,  const float* __restrict__ bs,
            const float* __restrict__ Wih, const float* __restrict__ bih,
            const float* __restrict__ Whh, const float* __restrict__ bhh,
            const float* __restrict__ W1,  const float* __restrict__ b1,
            const float* __restrict__ W2,  const float* __restrict__ b2,
            const float* __restrict__ gm,  const float* __restrict__ bm,
            float* __restrict__ out_slots, float* __restrict__ out_attn,
            int writeSlots, int writeAttn)
{
    __shared__ SmemUnion u;                           // 36 KB
    __shared__ __align__(16) float s_prev[KSLOT][HH];
    __shared__ __align__(16) float s_ln  [KSLOT][HH];
    __shared__ __align__(16) float q_s   [KSLOT][HH];
    __shared__ __align__(16) float u_s   [KSLOT][HH];
    __shared__ __align__(16) float s_new [KSLOT][HH];
    __shared__ __align__(16) float m_ln  [KSLOT][HH];

    const int b    = blockIdx.x;
    const int tid  = threadIdx.x;
    const int lane = tid & 31;
    const int warp = tid >> 5;

    if (tid < KSLOT*HH) s_prev[0][tid] = g_slots[b*KSLOT*HH + tid];
    __syncthreads();

    // --- LN(slots) ---
    if (warp < KSLOT) warp_ln_row(s_prev[warp], s_ln[warp], gs, bs, lane);
    __syncthreads();

    // --- q = s_ln @ Wq^T + bq, scale folded ---
    if (tid < HH) {
        const int j = tid;
        const float4* wr = (const float4*)(Wq + (size_t)j*HH);
        float d0 = 0.f, d1 = 0.f, d2 = 0.f;
        #pragma unroll 8
        for (int i = 0; i < HH/4; i++) {
            float4 w  = wr[i];
            float4 a0 = *(const float4*)&s_ln[0][i*4];
            float4 a1 = *(const float4*)&s_ln[1][i*4];
            float4 a2 = *(const float4*)&s_ln[2][i*4];
            d0 += w.x*a0.x + w.y*a0.y + w.z*a0.z + w.w*a0.w;
            d1 += w.x*a1.x + w.y*a1.y + w.z*a1.z + w.w*a1.w;
            d2 += w.x*a2.x + w.y*a2.y + w.z*a2.z + w.w*a2.w;
        }
        float bb = bq[j];
        q_s[0][j] = (d0 + bb) * SCALE;
        q_s[1][j] = (d1 + bb) * SCALE;
        q_s[2][j] = (d2 + bb) * SCALE;
    }
    __syncthreads();

    // --- Phase A: dots + softmax, thread handles tokens 2*tid, 2*tid+1 ---
    {
        const float* kTb = g_kT + (size_t)b * HH * NN + 2*tid;
        float a0=0.f,a1=0.f,b0v=0.f,b1v=0.f,c0=0.f,c1=0.f;
        #pragma unroll 8
        for (int d = 0; d < HH; d++) {
            float2 kv = *(const float2*)(kTb + (size_t)d * NN);
            float q0 = q_s[0][d], q1 = q_s[1][d], q2 = q_s[2][d];
            a0  = fmaf(q0, kv.x, a0);  a1  = fmaf(q0, kv.y, a1);
            b0v = fmaf(q1, kv.x, b0v); b1v = fmaf(q1, kv.y, b1v);
            c0  = fmaf(q2, kv.x, c0);  c1  = fmaf(q2, kv.y, c1);
        }
        // softmax over slots, token 0
        float mx0 = fmaxf(a0, fmaxf(b0v, c0));
        float e00 = expf(a0-mx0), e10 = expf(b0v-mx0), e20 = expf(c0-mx0);
        float inv0 = 1.f / (e00 + e10 + e20);
        float w00 = e00*inv0, w10 = e10*inv0, w20 = e20*inv0;
        // token 1
        float mx1 = fmaxf(a1, fmaxf(b1v, c1));
        float e01 = expf(a1-mx1), e11 = expf(b1v-mx1), e21 = expf(c1-mx1);
        float inv1 = 1.f / (e01 + e11 + e21);
        float w01 = e01*inv1, w11 = e11*inv1, w21 = e21*inv1;

        int n = 2*tid;
        *(float2*)&u.a.w[0][n] = make_float2(w00, w01);
        *(float2*)&u.a.w[1][n] = make_float2(w10, w11);
        *(float2*)&u.a.w[2][n] = make_float2(w20, w21);
        if (writeAttn) {
            float* ob = out_attn + (size_t)b * KSLOT * NN + n;
            *(float2*)(ob)        = make_float2(w00, w01);
            *(float2*)(ob + NN)   = make_float2(w10, w11);
            *(float2*)(ob + 2*NN) = make_float2(w20, w21);
        }
    }
    __syncthreads();

    // --- Phase B: updates = w @ v, warp-per-token strip ---
    {
        float a00=0,a01=0,a02=0,a03=0;
        float a10=0,a11=0,a12=0,a13=0;
        float a20=0,a21=0,a22=0,a23=0;
        const float* vb = g_v + (size_t)b*NN*HH;
        #pragma unroll 4
        for (int n = warp; n < NN; n += 16) {
            float w0 = u.a.w[0][n], w1 = u.a.w[1][n], w2 = u.a.w[2][n];
            float4 vv = *(const float4*)(vb + (size_t)n*HH + lane*4);
            a00 = fmaf(w0, vv.x, a00); a01 = fmaf(w0, vv.y, a01);
            a02 = fmaf(w0, vv.z, a02); a03 = fmaf(w0, vv.w, a03);
            a10 = fmaf(w1, vv.x, a10); a11 = fmaf(w1, vv.y, a11);
            a12 = fmaf(w1, vv.z, a12); a13 = fmaf(w1, vv.w, a13);
            a20 = fmaf(w2, vv.x, a20); a21 = fmaf(w2, vv.y, a21);
            a22 = fmaf(w2, vv.z, a22); a23 = fmaf(w2, vv.w, a23);
        }
        __syncwarp();
        *(float4*)&u.a.uacc[warp][0][lane*4] = make_float4(a00,a01,a02,a03);
        *(float4*)&u.a.uacc[warp][1][lane*4] = make_float4(a10,a11,a12,a13);
        *(float4*)&u.a.uacc[warp][2][lane*4] = make_float4(a20,a21,a22,a23);
    }
    __syncthreads();
    if (tid < KSLOT*HH) {
        int s = tid >> 7, j = tid & 127;
        float acc = 0.f;
        #pragma unroll
        for (int w = 0; w < 16; w++) acc += u.a.uacc[w][s][j];
        u_s[s][j] = acc;
    }
    __syncthreads();

    // --- GRU gates (union region reused: w/uacc dead, u_s holds result) ---
    if (tid < 3*HH) {
        const int o = tid;
        {
            const float4* wr = (const float4*)(Wih + (size_t)o*HH);
            float d0=0,d1=0,d2=0;
            #pragma unroll 4
            for (int i = 0; i < HH/4; i++) {
                float4 w  = wr[i];
                float4 x0 = *(const float4*)&u_s[0][i*4];
                float4 x1 = *(const float4*)&u_s[1][i*4];
                float4 x2 = *(const float4*)&u_s[2][i*4];
                d0 += w.x*x0.x + w.y*x0.y + w.z*x0.z + w.w*x0.w;
                d1 += w.x*x1.x + w.y*x1.y + w.z*x1.z + w.w*x1.w;
                d2 += w.x*x2.x + w.y*x2.y + w.z*x2.z + w.w*x2.w;
            }
            float bb = bih[o];
            u.g.gi[0][o] = d0+bb; u.g.gi[1][o] = d1+bb; u.g.gi[2][o] = d2+bb;
        }
        {
            const float4* wr = (const float4*)(Whh + (size_t)o*HH);
            float d0=0,d1=0,d2=0;
            #pragma unroll 4
            for (int i = 0; i < HH/4; i++) {
                float4 w  = wr[i];
                float4 x0 = *(const float4*)&s_prev[0][i*4];
                float4 x1 = *(const float4*)&s_prev[1][i*4];
                float4 x2 = *(const float4*)&s_prev[2][i*4];
                d0 += w.x*x0.x + w.y*x0.y + w.z*x0.z + w.w*x0.w;
                d1 += w.x*x1.x + w.y*x1.y + w.z*x1.z + w.w*x1.w;
                d2 += w.x*x2.x + w.y*x2.y + w.z*x2.z + w.w*x2.w;
            }
            float bb = bhh[o];
            u.g.gh[0][o] = d0+bb; u.g.gh[1][o] = d1+bb; u.g.gh[2][o] = d2+bb;
        }
    }
    __syncthreads();
    if (tid < KSLOT*HH) {
        int s = tid >> 7, j = tid & 127;
        float ir = u.g.gi[s][j], iz = u.g.gi[s][HH+j], inn = u.g.gi[s][2*HH+j];
        float hr = u.g.gh[s][j], hz = u.g.gh[s][HH+j], hn  = u.g.gh[s][2*HH+j];
        float r  = 1.f / (1.f + expf(-(ir+hr)));
        float z  = 1.f / (1.f + expf(-(iz+hz)));
        float nn = tanhf(inn + r*hn);
        s_new[s][j] = (1.f - z)*nn + z*s_prev[s][j];
    }
    __syncthreads();

    // --- MLP with residual ---
    if (warp < KSLOT) warp_ln_row(s_new[warp], m_ln[warp], gm, bm, lane);
    __syncthreads();
    if (tid < 2*HH) {
        const int jr = tid;
        const float4* wr = (const float4*)(W1 + (size_t)jr*HH);
        float d0=0,d1=0,d2=0;
        #pragma unroll 4
        for (int i = 0; i < HH/4; i++) {
            float4 w  = wr[i];
            float4 x0 = *(const float4*)&m_ln[0][i*4];
            float4 x1 = *(const float4*)&m_ln[1][i*4];
            float4 x2 = *(const float4*)&m_ln[2][i*4];
            d0 += w.x*x0.x + w.y*x0.y + w.z*x0.z + w.w*x0.w;
            d1 += w.x*x1.x + w.y*x1.y + w.z*x1.z + w.w*x1.w;
            d2 += w.x*x2.x + w.y*x2.y + w.z*x2.z + w.w*x2.w;
        }
        float bb = b1[jr];
        u.g.h1[0][jr] = geluf(d0+bb);
        u.g.h1[1][jr] = geluf(d1+bb);
        u.g.h1[2][jr] = geluf(d2+bb);
    }
    __syncthreads();
    if (tid < HH) {
        const int j = tid;
        const float4* wr = (const float4*)(W2 + (size_t)j*2*HH);
        float d0=0,d1=0,d2=0;
        #pragma unroll 4
        for (int i = 0; i < (2*HH)/4; i++) {
            float4 w  = wr[i];
            float4 x0 = *(const float4*)&u.g.h1[0][i*4];
            float4 x1 = *(const float4*)&u.g.h1[1][i*4];
            float4 x2 = *(const float4*)&u.g.h1[2][i*4];
            d0 += w.x*x0.x + w.y*x0.y + w.z*x0.z + w.w*x0.w;
            d1 += w.x*x1.x + w.y*x1.y + w.z*x1.z + w.w*x1.w;
            d2 += w.x*x2.x + w.y*x2.y + w.z*x2.z + w.w*x2.w;
        }
        float bb = b2[j];
        float f0 = s_new[0][j] + d0 + bb;
        float f1 = s_new[1][j] + d1 + bb;
        float f2 = s_new[2][j] + d2 + bb;
        g_slots[b*KSLOT*HH + 0*HH + j] = f0;
        g_slots[b*KSLOT*HH + 1*HH + j] = f1;
        g_slots[b*KSLOT*HH + 2*HH + j] = f2;
        if (writeSlots) {
            out_slots[(size_t)b*KSLOT*HH + 0*HH + j] = f0;
            out_slots[(size_t)b*KSLOT*HH + 1*HH + j] = f1;
            out_slots[(size_t)b*KSLOT*HH + 2*HH + j] = f2;
        }
    }
}

// ---------------------------------------------------------------------------
// Launch
// ---------------------------------------------------------------------------
extern "C" void kernel_launch(void* const* d_in, const int* in_sizes, int n_in,
                              void* d_out, int out_size)
{
    const float* patch = (const float*)d_in[0];
    const float* noise = (const float*)d_in[1];
    const float* smu   = (const float*)d_in[2];
    const float* slsig = (const float*)d_in[3];
    const float* Wp    = (const float*)d_in[4];
    const float* bp    = (const float*)d_in[5];
    const float* g_in  = (const float*)d_in[6];
    const float* b_in  = (const float*)d_in[7];
    const float* Wq    = (const float*)d_in[8];
    const float* bq    = (const float*)d_in[9];
    const float* Wk    = (const float*)d_in[10];
    const float* bk    = (const float*)d_in[11];
    const float* Wv    = (const float*)d_in[12];
    const float* bv    = (const float*)d_in[13];
    const float* Wih   = (const float*)d_in[14];
    const float* bih   = (const float*)d_in[15];
    const float* Whh   = (const float*)d_in[16];
    const float* bhh   = (const float*)d_in[17];
    const float* gs    = (const float*)d_in[18];
    const float* bs    = (const float*)d_in[19];
    const float* W1    = (const float*)d_in[20];
    const float* b1    = (const float*)d_in[21];
    const float* W2    = (const float*)d_in[22];
    const float* b2    = (const float*)d_in[23];
    const float* gm    = (const float*)d_in[24];
    const float* bm    = (const float*)d_in[25];

    float *pWpT, *pWkT, *pWvT, *pIn, *pKT, *pV;
    cudaGetSymbolAddress((void**)&pWpT, g_WpT);
    cudaGetSymbolAddress((void**)&pWkT, g_WkT);
    cudaGetSymbolAddress((void**)&pWvT, g_WvT);
    cudaGetSymbolAddress((void**)&pIn,  g_inputs);
    cudaGetSymbolAddress((void**)&pKT,  g_kT);
    cudaGetSymbolAddress((void**)&pV,   g_v);

    const int slotsElems = BB*KSLOT*HH;
    const int attnElems  = BB*KSLOT*NN;
    const int writeSlots = (out_size >= slotsElems) ? 1 : 0;
    const int writeAttn  = (out_size >= slotsElems + attnElems) ? 1 : 0;
    float* outSlots = (float*)d_out;
    float* outAttn  = (float*)d_out + slotsElems;

    // 1) transpose weights + init slots
    prep_kernel<<<192, 256>>>(Wp, Wk, Wv, noise, smu, slsig);

    // 2) inputs = LN(X @ Wp^T + bp)
    gemm128<DIN, true, false><<<MTOT/128, 256>>>(patch, pWpT, bp, g_in, b_in, pIn);

    // 3) k (transposed out), v projections
    gemm128<HH, false, true ><<<MTOT/128, 256>>>(pIn, pWkT, bk, nullptr, nullptr, pKT);
    gemm128<HH, false, false><<<MTOT/128, 256>>>(pIn, pWvT, bv, nullptr, nullptr, pV);

    // 4) 3 slot-attention iterations (fused)
    for (int it = 0; it < NITER; it++) {
        int last = (it == NITER - 1);
        iter_kernel<<<BB, 512>>>(Wq, bq, gs, bs, Wih, bih, Whh, bhh,
                                 W1, b1, W2, b2, gm, bm,
                                 outSlots, outAttn,
                                 last ? writeSlots : 0,
                                 last ? writeAttn  : 0);
    }
}

// round 8
// speedup vs baseline: 1.1827x; 1.0502x over previous
#include <cuda_runtime.h>
#include <math.h>

// Problem constants (fixed bench shapes)
#define BB    128
#define NN    1024
#define DIN   192
#define HH    128
#define KSLOT 3
#define NITER 3
#define EPSX  1e-5f
#define MTOT  (BB*NN)              // 131072 token rows
#define SCALE 0.08838834764831845f // 1/sqrt(128)

typedef unsigned long long ull;

// ---------------------------------------------------------------------------
// Scratch (device globals: allocation-free rule)
// ---------------------------------------------------------------------------
__device__ float g_WpT[DIN*HH];
__device__ float g_WkT[HH*HH];
__device__ float g_WvT[HH*HH];
__device__ float g_inputs[(size_t)MTOT*HH];  // 67 MB
__device__ float g_kT[(size_t)MTOT*HH];      // 67 MB, layout [B][H][N]
__device__ float g_v[(size_t)MTOT*HH];       // 67 MB, layout [B][N][H]
__device__ float g_slots[BB*KSLOT*HH];

// f32x2 helpers ------------------------------------------------------------
__device__ __forceinline__ ull splat2(float a) {
    ull r; asm("mov.b64 %0, {%1, %1};" : "=l"(r) : "f"(a)); return r;
}
__device__ __forceinline__ void fma2(ull& d, ull a, ull b) {
    asm("fma.rn.f32x2 %0, %1, %2, %0;" : "+l"(d) : "l"(a), "l"(b));
}
__device__ __forceinline__ float2 unpack2(ull v) {
    float2 r; asm("mov.b64 {%0, %1}, %2;" : "=f"(r.x), "=f"(r.y) : "l"(v)); return r;
}

// ---------------------------------------------------------------------------
// Prep: transpose weights; init slots
// ---------------------------------------------------------------------------
__global__ void prep_kernel(const float* __restrict__ Wp,
                            const float* __restrict__ Wk,
                            const float* __restrict__ Wv,
                            const float* __restrict__ noise,
                            const float* __restrict__ slot_mu,
                            const float* __restrict__ slot_lsig)
{
    int i = blockIdx.x * blockDim.x + threadIdx.x;
    if (i < HH*DIN) {                 // Wp: [128][192] -> WpT[192][128]
        int r = i / DIN, c = i % DIN;
        g_WpT[c*HH + r] = Wp[i];
    }
    if (i < HH*HH) {                  // Wk, Wv transposed
        int r = i >> 7, c = i & 127;
        g_WkT[c*HH + r] = Wk[i];
        g_WvT[c*HH + r] = Wv[i];
    }
    if (i < BB*KSLOT*HH) {
        int kh = i % (KSLOT*HH);
        g_slots[i] = slot_mu[kh] + expf(slot_lsig[kh]) * noise[i];
    }
}

// ---------------------------------------------------------------------------
// SGEMM, double-buffered smem, ONE __syncthreads per k-tile.
// 128x128 tile / block, 256 threads, 8x8 register tile as f32x2 pairs.
// TRANS_OUT=1: write output transposed as [b][feature][n] (for kT).
// ---------------------------------------------------------------------------
template<int KDIM, bool DO_LN, bool TRANS_OUT>
__global__ void __launch_bounds__(256)
gemm128(const float* __restrict__ A, const float* __restrict__ Bm,
        const float* __restrict__ bias, const float* __restrict__ gamma,
        const float* __restrict__ beta, float* __restrict__ out)
{
    __shared__ __align__(16) float As[2][8][132];   // [buf][k][m]
    __shared__ __align__(16) float Bs[2][8][128];   // [buf][k][n]
    __shared__ float psum[16][129];
    __shared__ float psq [16][129];
    __shared__ float smu[128], srs[128];

    const int tid = threadIdx.x;
    const int tx = tid & 15, ty = tid >> 4;
    const int m0 = blockIdx.x * 128;

    const int aRow = tid >> 1;
    const int aCol = (tid & 1) * 4;
    const int bRow = tid >> 5;
    const int bCol = (tid & 31) * 4;

    const float* Ab = A + (size_t)m0 * KDIM;
    const int NT = KDIM / 8;

    ull acc2[8][4];
    #pragma unroll
    for (int i = 0; i < 8; i++)
        #pragma unroll
        for (int j = 0; j < 4; j++) acc2[i][j] = 0ull;

    // prologue: tile 0 -> smem buf 0
    {
        float4 a4 = *(const float4*)(Ab + (size_t)aRow * KDIM + aCol);
        As[0][aCol+0][aRow] = a4.x;
        As[0][aCol+1][aRow] = a4.y;
        As[0][aCol+2][aRow] = a4.z;
        As[0][aCol+3][aRow] = a4.w;
        *(float4*)&Bs[0][bRow][bCol] =
            *(const float4*)(Bm + (size_t)bRow * HH + bCol);
    }
    __syncthreads();

    for (int t = 0; t < NT; t++) {
        const int buf = t & 1;
        float4 na, nb;
        if (t + 1 < NT) {   // prefetch next tile into regs (overlaps compute)
            na = *(const float4*)(Ab + (size_t)aRow * KDIM + ((t+1)*8 + aCol));
            nb = *(const float4*)(Bm + (size_t)((t+1)*8 + bRow) * HH + bCol);
        }
        #pragma unroll
        for (int kk = 0; kk < 8; kk++) {
            float a[8];
            *(float4*)&a[0] = *(const float4*)&As[buf][kk][ty*8];
            *(float4*)&a[4] = *(const float4*)&As[buf][kk][ty*8+4];
            ull b2[4];
            const ull* bp = (const ull*)&Bs[buf][kk][tx*8];
            b2[0] = bp[0]; b2[1] = bp[1]; b2[2] = bp[2]; b2[3] = bp[3];
            #pragma unroll
            for (int i = 0; i < 8; i++) {
                ull av = splat2(a[i]);
                fma2(acc2[i][0], av, b2[0]);
                fma2(acc2[i][1], av, b2[1]);
                fma2(acc2[i][2], av, b2[2]);
                fma2(acc2[i][3], av, b2[3]);
            }
        }
        if (t + 1 < NT) {
            // buf^1 was last read at iter t-1; all threads passed that
            // iteration's barrier, so overwriting before this sync is safe.
            const int nbuf = buf ^ 1;
            As[nbuf][aCol+0][aRow] = na.x;
            As[nbuf][aCol+1][aRow] = na.y;
            As[nbuf][aCol+2][aRow] = na.z;
            As[nbuf][aCol+3][aRow] = na.w;
            *(float4*)&Bs[nbuf][bRow][bCol] = nb;
            __syncthreads();
        }
    }

    // unpack + bias
    float accf[8][8];
    float bj[8];
    #pragma unroll
    for (int j = 0; j < 8; j++) bj[j] = bias[tx*8 + j];
    #pragma unroll
    for (int i = 0; i < 8; i++)
        #pragma unroll
        for (int jp = 0; jp < 4; jp++) {
            float2 f = unpack2(acc2[i][jp]);
            accf[i][2*jp]   = f.x + bj[2*jp];
            accf[i][2*jp+1] = f.y + bj[2*jp+1];
        }

    if (DO_LN) {
        __syncthreads();   // protect psum/psq (aliasing-free but order safety)
        #pragma unroll
        for (int i = 0; i < 8; i++) {
            int row = ty*8 + i;
            float s = 0.f, q = 0.f;
            #pragma unroll
            for (int j = 0; j < 8; j++) { s += accf[i][j]; q += accf[i][j]*accf[i][j]; }
            psum[tx][row] = s;
            psq [tx][row] = q;
        }
        __syncthreads();
        if (tid < 128) {
            float s = 0.f, q = 0.f;
            #pragma unroll
            for (int t = 0; t < 16; t++) { s += psum[t][tid]; q += psq[t][tid]; }
            float mu  = s * (1.f/128.f);
            float var = q * (1.f/128.f) - mu*mu;
            smu[tid] = mu;
            srs[tid] = rsqrtf(var + EPSX);
        }
        __syncthreads();
        float gj[8], b2j[8];
        #pragma unroll
        for (int j = 0; j < 8; j++) { gj[j] = gamma[tx*8+j]; b2j[j] = beta[tx*8+j]; }
        #pragma unroll
        for (int i = 0; i < 8; i++) {
            int row = ty*8 + i;
            float mu = smu[row], rs = srs[row];
            float o[8];
            #pragma unroll
            for (int j = 0; j < 8; j++) o[j] = (accf[i][j]-mu)*rs*gj[j] + b2j[j];
            float4* dst = (float4*)(out + (size_t)(m0+row)*HH + tx*8);
            dst[0] = make_float4(o[0], o[1], o[2], o[3]);
            dst[1] = make_float4(o[4], o[5], o[6], o[7]);
        }
    } else if (TRANS_OUT) {
        // out layout [b][feature][n]; all 128 rows of this block share one b
        const int bidx = m0 >> 10, n0 = m0 & 1023;
        float* Ob = out + (size_t)bidx * HH * NN + n0;
        #pragma unroll
        for (int j = 0; j < 8; j++) {
            int feat = tx*8 + j;
            float* row = Ob + (size_t)feat * NN + ty*8;
            *(float4*)(row)     = make_float4(accf[0][j], accf[1][j], accf[2][j], accf[3][j]);
            *(float4*)(row + 4) = make_float4(accf[4][j], accf[5][j], accf[6][j], accf[7][j]);
        }
    } else {
        #pragma unroll
        for (int i = 0; i < 8; i++) {
            int row = ty*8 + i;
            float4* dst = (float4*)(out + (size_t)(m0+row)*HH + tx*8);
            dst[0] = make_float4(accf[i][0], accf[i][1], accf[i][2], accf[i][3]);
            dst[1] = make_float4(accf[i][4], accf[i][5], accf[i][6], accf[i][7]);
        }
    }
}

// ---------------------------------------------------------------------------
// Fused per-iteration kernel: one block per batch element, 1024 threads.
// Phase A: thread-per-token dots from kT (coalesced, no shuffles), softmax
//          over 3 slots thread-local, weights to shared.
// Phase B: 32 warp-partials for w@v accumulation.
// Then GRU + MLP as small shared-memory GEMVs.
// ---------------------------------------------------------------------------
__device__ __forceinline__ float geluf(float x) {
    return 0.5f * x * (1.f + erff(x * 0.70710678118654752f));
}

__device__ __forceinline__ void warp_ln_row(const float* __restrict__ src,
                                            float* __restrict__ dst,
                                            const float* __restrict__ gamma,
                                            const float* __restrict__ beta,
                                            int lane)
{
    float4 xv = *(const float4*)(src + lane*4);
    float s = xv.x + xv.y + xv.z + xv.w;
    #pragma unroll
    for (int off = 16; off > 0; off >>= 1) s += __shfl_xor_sync(0xffffffffu, s, off);
    float mu = s * (1.f/128.f);
    float d0 = xv.x-mu, d1 = xv.y-mu, d2 = xv.z-mu, d3 = xv.w-mu;
    float q = d0*d0 + d1*d1 + d2*d2 + d3*d3;
    #pragma unroll
    for (int off = 16; off > 0; off >>= 1) q += __shfl_xor_sync(0xffffffffu, q, off);
    float rs = rsqrtf(q * (1.f/128.f) + EPSX);
    float4 g4 = *(const float4*)(gamma + lane*4);
    float4 b4 = *(const float4*)(beta  + lane*4);
    float4 o;
    o.x = d0*rs*g4.x + b4.x;
    o.y = d1*rs*g4.y + b4.y;
    o.z = d2*rs*g4.z + b4.z;
    o.w = d3*rs*g4.w + b4.w;
    *(float4*)(dst + lane*4) = o;
}

struct SmemAttn {
    float w[KSLOT][NN];          // 12 KB
    float uacc[32][KSLOT][HH];   // 48 KB
};
struct SmemGru {
    float gi[KSLOT][3*HH];
    float gh[KSLOT][3*HH];
    float h1[KSLOT][2*HH];
};
struct IterSmem {
    union { SmemAttn a; SmemGru g; } u;
    float s_prev[KSLOT][HH];
    float s_ln  [KSLOT][HH];
    float q_s   [KSLOT][HH];
    float u_s   [KSLOT][HH];
    float s_new [KSLOT][HH];
    float m_ln  [KSLOT][HH];
};

__global__ void __launch_bounds__(1024)
iter_kernel(const float* __restrict__ Wq,  const float* __restrict__ bq,
            const float* __restrict__ gs,  const float* __restrict__ bs,
            const float* __restrict__ Wih, const float* __restrict__ bih,
            const float* __restrict__ Whh, const float* __restrict__ bhh,
            const float* __restrict__ W1,  const float* __restrict__ b1,
            const float* __restrict__ W2,  const float* __restrict__ b2,
            const float* __restrict__ gm,  const float* __restrict__ bm,
            float* __restrict__ out_slots, float* __restrict__ out_attn,
            int writeSlots, int writeAttn)
{
    extern __shared__ __align__(16) char smem_raw[];
    IterSmem& S = *reinterpret_cast<IterSmem*>(smem_raw);

    const int b    = blockIdx.x;
    const int tid  = threadIdx.x;
    const int lane = tid & 31;
    const int warp = tid >> 5;

    if (tid < KSLOT*HH) S.s_prev[0][tid] = g_slots[b*KSLOT*HH + tid];
    __syncthreads();

    // --- LN(slots) ---
    if (warp < KSLOT) warp_ln_row(S.s_prev[warp], S.s_ln[warp], gs, bs, lane);
    __syncthreads();

    // --- q = s_ln @ Wq^T + bq, scale folded ---
    if (tid < HH) {
        const int j = tid;
        const float4* wr = (const float4*)(Wq + (size_t)j*HH);
        float d0 = 0.f, d1 = 0.f, d2 = 0.f;
        #pragma unroll 8
        for (int i = 0; i < HH/4; i++) {
            float4 w  = wr[i];
            float4 a0 = *(const float4*)&S.s_ln[0][i*4];
            float4 a1 = *(const float4*)&S.s_ln[1][i*4];
            float4 a2 = *(const float4*)&S.s_ln[2][i*4];
            d0 += w.x*a0.x + w.y*a0.y + w.z*a0.z + w.w*a0.w;
            d1 += w.x*a1.x + w.y*a1.y + w.z*a1.z + w.w*a1.w;
            d2 += w.x*a2.x + w.y*a2.y + w.z*a2.z + w.w*a2.w;
        }
        float bb = bq[j];
        S.q_s[0][j] = (d0 + bb) * SCALE;
        S.q_s[1][j] = (d1 + bb) * SCALE;
        S.q_s[2][j] = (d2 + bb) * SCALE;
    }
    __syncthreads();

    // --- Phase A: dot products + softmax, one token per thread ---
    {
        const float* kTb = g_kT + (size_t)b * HH * NN + tid;
        float d0 = 0.f, d1 = 0.f, d2 = 0.f;
        #pragma unroll 8
        for (int d = 0; d < HH; d++) {
            float kv = kTb[(size_t)d * NN];
            d0 = fmaf(S.q_s[0][d], kv, d0);
            d1 = fmaf(S.q_s[1][d], kv, d1);
            d2 = fmaf(S.q_s[2][d], kv, d2);
        }
        float mx = fmaxf(d0, fmaxf(d1, d2));
        float e0 = expf(d0-mx), e1 = expf(d1-mx), e2 = expf(d2-mx);
        float inv = 1.f / (e0 + e1 + e2);
        float w0 = e0*inv, w1 = e1*inv, w2 = e2*inv;
        S.u.a.w[0][tid] = w0;
        S.u.a.w[1][tid] = w1;
        S.u.a.w[2][tid] = w2;
        if (writeAttn) {
            float* ob = out_attn + (size_t)b * KSLOT * NN + tid;
            ob[0]    = w0;
            ob[NN]   = w1;
            ob[2*NN] = w2;
        }
    }
    __syncthreads();

    // --- Phase B: updates = w @ v, 32 warp-partials ---
    {
        float a00=0,a01=0,a02=0,a03=0;
        float a10=0,a11=0,a12=0,a13=0;
        float a20=0,a21=0,a22=0,a23=0;
        const float* vb = g_v + (size_t)b*NN*HH;
        #pragma unroll 4
        for (int n = warp; n < NN; n += 32) {
            float w0 = S.u.a.w[0][n], w1 = S.u.a.w[1][n], w2 = S.u.a.w[2][n];
            float4 vv = *(const float4*)(vb + (size_t)n*HH + lane*4);
            a00 = fmaf(w0, vv.x, a00); a01 = fmaf(w0, vv.y, a01);
            a02 = fmaf(w0, vv.z, a02); a03 = fmaf(w0, vv.w, a03);
            a10 = fmaf(w1, vv.x, a10); a11 = fmaf(w1, vv.y, a11);
            a12 = fmaf(w1, vv.z, a12); a13 = fmaf(w1, vv.w, a13);
            a20 = fmaf(w2, vv.x, a20); a21 = fmaf(w2, vv.y, a21);
            a22 = fmaf(w2, vv.z, a22); a23 = fmaf(w2, vv.w, a23);
        }
        *(float4*)&S.u.a.uacc[warp][0][lane*4] = make_float4(a00,a01,a02,a03);
        *(float4*)&S.u.a.uacc[warp][1][lane*4] = make_float4(a10,a11,a12,a13);
        *(float4*)&S.u.a.uacc[warp][2][lane*4] = make_float4(a20,a21,a22,a23);
    }
    __syncthreads();
    if (tid < KSLOT*HH) {
        int s = tid >> 7, j = tid & 127;
        float acc = 0.f;
        #pragma unroll
        for (int w = 0; w < 32; w++) acc += S.u.a.uacc[w][s][j];
        S.u_s[s][j] = acc;
    }
    __syncthreads();

    // --- GRU gates (union reused: w/uacc dead, u_s holds result) ---
    if (tid < 3*HH) {
        const int o = tid;
        {
            const float4* wr = (const float4*)(Wih + (size_t)o*HH);
            float d0=0,d1=0,d2=0;
            #pragma unroll 4
            for (int i = 0; i < HH/4; i++) {
                float4 w  = wr[i];
                float4 x0 = *(const float4*)&S.u_s[0][i*4];
                float4 x1 = *(const float4*)&S.u_s[1][i*4];
                float4 x2 = *(const float4*)&S.u_s[2][i*4];
                d0 += w.x*x0.x + w.y*x0.y + w.z*x0.z + w.w*x0.w;
                d1 += w.x*x1.x + w.y*x1.y + w.z*x1.z + w.w*x1.w;
                d2 += w.x*x2.x + w.y*x2.y + w.z*x2.z + w.w*x2.w;
            }
            float bb = bih[o];
            S.u.g.gi[0][o] = d0+bb; S.u.g.gi[1][o] = d1+bb; S.u.g.gi[2][o] = d2+bb;
        }
        {
            const float4* wr = (const float4*)(Whh + (size_t)o*HH);
            float d0=0,d1=0,d2=0;
            #pragma unroll 4
            for (int i = 0; i < HH/4; i++) {
                float4 w  = wr[i];
                float4 x0 = *(const float4*)&S.s_prev[0][i*4];
                float4 x1 = *(const float4*)&S.s_prev[1][i*4];
                float4 x2 = *(const float4*)&S.s_prev[2][i*4];
                d0 += w.x*x0.x + w.y*x0.y + w.z*x0.z + w.w*x0.w;
                d1 += w.x*x1.x + w.y*x1.y + w.z*x1.z + w.w*x1.w;
                d2 += w.x*x2.x + w.y*x2.y + w.z*x2.z + w.w*x2.w;
            }
            float bb = bhh[o];
            S.u.g.gh[0][o] = d0+bb; S.u.g.gh[1][o] = d1+bb; S.u.g.gh[2][o] = d2+bb;
        }
    }
    __syncthreads();
    if (tid < KSLOT*HH) {
        int s = tid >> 7, j = tid & 127;
        float ir = S.u.g.gi[s][j], iz = S.u.g.gi[s][HH+j], inn = S.u.g.gi[s][2*HH+j];
        float hr = S.u.g.gh[s][j], hz = S.u.g.gh[s][HH+j], hn  = S.u.g.gh[s][2*HH+j];
        float r  = 1.f / (1.f + expf(-(ir+hr)));
        float z  = 1.f / (1.f + expf(-(iz+hz)));
        float nn = tanhf(inn + r*hn);
        S.s_new[s][j] = (1.f - z)*nn + z*S.s_prev[s][j];
    }
    __syncthreads();

    // --- MLP with residual ---
    if (warp < KSLOT) warp_ln_row(S.s_new[warp], S.m_ln[warp], gm, bm, lane);
    __syncthreads();
    if (tid < 2*HH) {
        const int jr = tid;
        const float4* wr = (const float4*)(W1 + (size_t)jr*HH);
        float d0=0,d1=0,d2=0;
        #pragma unroll 4
        for (int i = 0; i < HH/4; i++) {
            float4 w  = wr[i];
            float4 x0 = *(const float4*)&S.m_ln[0][i*4];
            float4 x1 = *(const float4*)&S.m_ln[1][i*4];
            float4 x2 = *(const float4*)&S.m_ln[2][i*4];
            d0 += w.x*x0.x + w.y*x0.y + w.z*x0.z + w.w*x0.w;
            d1 += w.x*x1.x + w.y*x1.y + w.z*x1.z + w.w*x1.w;
            d2 += w.x*x2.x + w.y*x2.y + w.z*x2.z + w.w*x2.w;
        }
        float bb = b1[jr];
        S.u.g.h1[0][jr] = geluf(d0+bb);
        S.u.g.h1[1][jr] = geluf(d1+bb);
        S.u.g.h1[2][jr] = geluf(d2+bb);
    }
    __syncthreads();
    if (tid < HH) {
        const int j = tid;
        const float4* wr = (const float4*)(W2 + (size_t)j*2*HH);
        float d0=0,d1=0,d2=0;
        #pragma unroll 4
        for (int i = 0; i < (2*HH)/4; i++) {
            float4 w  = wr[i];
            float4 x0 = *(const float4*)&S.u.g.h1[0][i*4];
            float4 x1 = *(const float4*)&S.u.g.h1[1][i*4];
            float4 x2 = *(const float4*)&S.u.g.h1[2][i*4];
            d0 += w.x*x0.x + w.y*x0.y + w.z*x0.z + w.w*x0.w;
            d1 += w.x*x1.x + w.y*x1.y + w.z*x1.z + w.w*x1.w;
            d2 += w.x*x2.x + w.y*x2.y + w.z*x2.z + w.w*x2.w;
        }
        float bb = b2[j];
        float f0 = S.s_new[0][j] + d0 + bb;
        float f1 = S.s_new[1][j] + d1 + bb;
        float f2 = S.s_new[2][j] + d2 + bb;
        g_slots[b*KSLOT*HH + 0*HH + j] = f0;
        g_slots[b*KSLOT*HH + 1*HH + j] = f1;
        g_slots[b*KSLOT*HH + 2*HH + j] = f2;
        if (writeSlots) {
            out_slots[(size_t)b*KSLOT*HH + 0*HH + j] = f0;
            out_slots[(size_t)b*KSLOT*HH + 1*HH + j] = f1;
            out_slots[(size_t)b*KSLOT*HH + 2*HH + j] = f2;
        }
    }
}

// ---------------------------------------------------------------------------
// Launch
// ---------------------------------------------------------------------------
extern "C" void kernel_launch(void* const* d_in, const int* in_sizes, int n_in,
                              void* d_out, int out_size)
{
    const float* patch = (const float*)d_in[0];
    const float* noise = (const float*)d_in[1];
    const float* smu   = (const float*)d_in[2];
    const float* slsig = (const float*)d_in[3];
    const float* Wp    = (const float*)d_in[4];
    const float* bp    = (const float*)d_in[5];
    const float* g_in  = (const float*)d_in[6];
    const float* b_in  = (const float*)d_in[7];
    const float* Wq    = (const float*)d_in[8];
    const float* bq    = (const float*)d_in[9];
    const float* Wk    = (const float*)d_in[10];
    const float* bk    = (const float*)d_in[11];
    const float* Wv    = (const float*)d_in[12];
    const float* bv    = (const float*)d_in[13];
    const float* Wih   = (const float*)d_in[14];
    const float* bih   = (const float*)d_in[15];
    const float* Whh   = (const float*)d_in[16];
    const float* bhh   = (const float*)d_in[17];
    const float* gs    = (const float*)d_in[18];
    const float* bs    = (const float*)d_in[19];
    const float* W1    = (const float*)d_in[20];
    const float* b1    = (const float*)d_in[21];
    const float* W2    = (const float*)d_in[22];
    const float* b2    = (const float*)d_in[23];
    const float* gm    = (const float*)d_in[24];
    const float* bm    = (const float*)d_in[25];

    float *pWpT, *pWkT, *pWvT, *pIn, *pKT, *pV;
    cudaGetSymbolAddress((void**)&pWpT, g_WpT);
    cudaGetSymbolAddress((void**)&pWkT, g_WkT);
    cudaGetSymbolAddress((void**)&pWvT, g_WvT);
    cudaGetSymbolAddress((void**)&pIn,  g_inputs);
    cudaGetSymbolAddress((void**)&pKT,  g_kT);
    cudaGetSymbolAddress((void**)&pV,   g_v);

    const int slotsElems = BB*KSLOT*HH;
    const int attnElems  = BB*KSLOT*NN;
    const int writeSlots = (out_size >= slotsElems) ? 1 : 0;
    const int writeAttn  = (out_size >= slotsElems + attnElems) ? 1 : 0;
    float* outSlots = (float*)d_out;
    float* outAttn  = (float*)d_out + slotsElems;

    static int smemSet = 0;
    const int iterSmem = (int)sizeof(IterSmem);
    if (!smemSet) {
        cudaFuncSetAttribute(iter_kernel,
                             cudaFuncAttributeMaxDynamicSharedMemorySize, iterSmem);
        smemSet = 1;
    }

    // 1) transpose weights + init slots
    prep_kernel<<<192, 256>>>(Wp, Wk, Wv, noise, smu, slsig);

    // 2) inputs = LN(X @ Wp^T + bp)
    gemm128<DIN, true, false><<<MTOT/128, 256>>>(patch, pWpT, bp, g_in, b_in, pIn);

    // 3) k (transposed out), v projections
    gemm128<HH, false, true ><<<MTOT/128, 256>>>(pIn, pWkT, bk, nullptr, nullptr, pKT);
    gemm128<HH, false, false><<<MTOT/128, 256>>>(pIn, pWvT, bv, nullptr, nullptr, pV);

    // 4) 3 slot-attention iterations (fused)
    for (int it = 0; it < NITER; it++) {
        int last = (it == NITER - 1);
        iter_kernel<<<BB, 1024, iterSmem>>>(Wq, bq, gs, bs, Wih, bih, Whh, bhh,
                                            W1, b1, W2, b2, gm, bm,
                                            outSlots, outAttn,
                                            last ? writeSlots : 0,
                                            last ? writeAttn  : 0);
    }
}

// round 14
// speedup vs baseline: 1.9709x; 1.6664x over previous
#include <cuda_runtime.h>
#include <math.h>

// Problem constants (fixed bench shapes)
#define BB    128
#define NN    1024
#define DIN   192
#define HH    128
#define KSLOT 3
#define NITER 3
#define EPSX  1e-5f
#define MTOT  (BB*NN)              // 131072 token rows
#define SCALE 0.08838834764831845f // 1/sqrt(128)

typedef unsigned long long ull;

// ---------------------------------------------------------------------------
// Scratch (device globals: allocation-free rule)
// ---------------------------------------------------------------------------
__device__ float g_WpT[DIN*HH];
__device__ float g_inputs[(size_t)MTOT*HH];  // 67 MB
__device__ float g_slots[BB*KSLOT*HH];

// f32x2 helpers ------------------------------------------------------------
__device__ __forceinline__ ull splat2(float a) {
    ull r; asm("mov.b64 %0, {%1, %1};" : "=l"(r) : "f"(a)); return r;
}
__device__ __forceinline__ void fma2(ull& d, ull a, ull b) {
    asm("fma.rn.f32x2 %0, %1, %2, %0;" : "+l"(d) : "l"(a), "l"(b));
}
__device__ __forceinline__ float2 unpack2(ull v) {
    float2 r; asm("mov.b64 {%0, %1}, %2;" : "=f"(r.x), "=f"(r.y) : "l"(v)); return r;
}

// ---------------------------------------------------------------------------
// Prep: transpose Wp for coalesced GEMM B-loads; init slots
// ---------------------------------------------------------------------------
__global__ void prep_kernel(const float* __restrict__ Wp,
                            const float* __restrict__ noise,
                            const float* __restrict__ slot_mu,
                            const float* __restrict__ slot_lsig)
{
    int i = blockIdx.x * blockDim.x + threadIdx.x;
    if (i < HH*DIN) {                 // Wp: [128][192] -> WpT[192][128]
        int r = i / DIN, c = i % DIN;
        g_WpT[c*HH + r] = Wp[i];
    }
    if (i < BB*KSLOT*HH) {            // slots = mu + exp(log_sigma)*noise
        int kh = i % (KSLOT*HH);
        g_slots[i] = slot_mu[kh] + expf(slot_lsig[kh]) * noise[i];
    }
}

// ---------------------------------------------------------------------------
// SGEMM (R8, proven): double-buffered smem, one __syncthreads per k-tile,
// f32x2 FMA register tiles, LayerNorm epilogue. 128x128 per block, 256 thr.
// ---------------------------------------------------------------------------
template<int KDIM>
__global__ void __launch_bounds__(256)
gemm_ln(const float* __restrict__ A, const float* __restrict__ Bm,
        const float* __restrict__ bias, const float* __restrict__ gamma,
        const float* __restrict__ beta, float* __restrict__ out)
{
    __shared__ __align__(16) float As[2][8][132];   // [buf][k][m]
    __shared__ __align__(16) float Bs[2][8][128];   // [buf][k][n]
    __shared__ float psum[16][129];
    __shared__ float psq [16][129];
    __shared__ float smu[128], srs[128];

    const int tid = threadIdx.x;
    const int tx = tid & 15, ty = tid >> 4;
    const int m0 = blockIdx.x * 128;

    const int aRow = tid >> 1;
    const int aCol = (tid & 1) * 4;
    const int bRow = tid >> 5;
    const int bCol = (tid & 31) * 4;

    const float* Ab = A + (size_t)m0 * KDIM;
    const int NT = KDIM / 8;

    ull acc2[8][4];
    #pragma unroll
    for (int i = 0; i < 8; i++)
        #pragma unroll
        for (int j = 0; j < 4; j++) acc2[i][j] = 0ull;

    {
        float4 a4 = *(const float4*)(Ab + (size_t)aRow * KDIM + aCol);
        As[0][aCol+0][aRow] = a4.x;
        As[0][aCol+1][aRow] = a4.y;
        As[0][aCol+2][aRow] = a4.z;
        As[0][aCol+3][aRow] = a4.w;
        *(float4*)&Bs[0][bRow][bCol] =
            *(const float4*)(Bm + (size_t)bRow * HH + bCol);
    }
    __syncthreads();

    for (int t = 0; t < NT; t++) {
        const int buf = t & 1;
        float4 na, nb;
        if (t + 1 < NT) {
            na = *(const float4*)(Ab + (size_t)aRow * KDIM + ((t+1)*8 + aCol));
            nb = *(const float4*)(Bm + (size_t)((t+1)*8 + bRow) * HH + bCol);
        }
        #pragma unroll
        for (int kk = 0; kk < 8; kk++) {
            float a[8];
            *(float4*)&a[0] = *(const float4*)&As[buf][kk][ty*8];
            *(float4*)&a[4] = *(const float4*)&As[buf][kk][ty*8+4];
            ull b2[4];
            const ull* bp = (const ull*)&Bs[buf][kk][tx*8];
            b2[0] = bp[0]; b2[1] = bp[1]; b2[2] = bp[2]; b2[3] = bp[3];
            #pragma unroll
            for (int i = 0; i < 8; i++) {
                ull av = splat2(a[i]);
                fma2(acc2[i][0], av, b2[0]);
                fma2(acc2[i][1], av, b2[1]);
                fma2(acc2[i][2], av, b2[2]);
                fma2(acc2[i][3], av, b2[3]);
            }
        }
        if (t + 1 < NT) {
            const int nbuf = buf ^ 1;
            As[nbuf][aCol+0][aRow] = na.x;
            As[nbuf][aCol+1][aRow] = na.y;
            As[nbuf][aCol+2][aRow] = na.z;
            As[nbuf][aCol+3][aRow] = na.w;
            *(float4*)&Bs[nbuf][bRow][bCol] = nb;
            __syncthreads();
        }
    }

    float accf[8][8];
    float bj[8];
    #pragma unroll
    for (int j = 0; j < 8; j++) bj[j] = bias[tx*8 + j];
    #pragma unroll
    for (int i = 0; i < 8; i++)
        #pragma unroll
        for (int jp = 0; jp < 4; jp++) {
            float2 f = unpack2(acc2[i][jp]);
            accf[i][2*jp]   = f.x + bj[2*jp];
            accf[i][2*jp+1] = f.y + bj[2*jp+1];
        }

    __syncthreads();
    #pragma unroll
    for (int i = 0; i < 8; i++) {
        int row = ty*8 + i;
        float s = 0.f, q = 0.f;
        #pragma unroll
        for (int j = 0; j < 8; j++) { s += accf[i][j]; q += accf[i][j]*accf[i][j]; }
        psum[tx][row] = s;
        psq [tx][row] = q;
    }
    __syncthreads();
    if (tid < 128) {
        float s = 0.f, q = 0.f;
        #pragma unroll
        for (int t = 0; t < 16; t++) { s += psum[t][tid]; q += psq[t][tid]; }
        float mu  = s * (1.f/128.f);
        float var = q * (1.f/128.f) - mu*mu;
        smu[tid] = mu;
        srs[tid] = rsqrtf(var + EPSX);
    }
    __syncthreads();
    float gj[8], b2j[8];
    #pragma unroll
    for (int j = 0; j < 8; j++) { gj[j] = gamma[tx*8+j]; b2j[j] = beta[tx*8+j]; }
    #pragma unroll
    for (int i = 0; i < 8; i++) {
        int row = ty*8 + i;
        float mu = smu[row], rs = srs[row];
        float o[8];
        #pragma unroll
        for (int j = 0; j < 8; j++) o[j] = (accf[i][j]-mu)*rs*gj[j] + b2j[j];
        float4* dst = (float4*)(out + (size_t)(m0+row)*HH + tx*8);
        dst[0] = make_float4(o[0], o[1], o[2], o[3]);
        dst[1] = make_float4(o[4], o[5], o[6], o[7]);
    }
}

// ---------------------------------------------------------------------------
// Fused per-iteration kernel. One block per batch element, 1024 threads.
// Key algebra: k and v are NEVER materialized.
//   logits_sn = (q_s@Wk)·in_n + q_s·bk
//   updates_s = (Σ_n w_sn·in_n)@Wv^T + (Σ_n w_sn)·bv
// One streaming pass over `inputs` per iteration (warp-per-token).
// ---------------------------------------------------------------------------
__device__ __forceinline__ float geluf(float x) {
    return 0.5f * x * (1.f + erff(x * 0.70710678118654752f));
}

__device__ __forceinline__ void warp_ln_row(const float* __restrict__ src,
                                            float* __restrict__ dst,
                                            const float* __restrict__ gamma,
                                            const float* __restrict__ beta,
                                            int lane)
{
    float4 xv = *(const float4*)(src + lane*4);
    float s = xv.x + xv.y + xv.z + xv.w;
    #pragma unroll
    for (int off = 16; off > 0; off >>= 1) s += __shfl_xor_sync(0xffffffffu, s, off);
    float mu = s * (1.f/128.f);
    float d0 = xv.x-mu, d1 = xv.y-mu, d2 = xv.z-mu, d3 = xv.w-mu;
    float q = d0*d0 + d1*d1 + d2*d2 + d3*d3;
    #pragma unroll
    for (int off = 16; off > 0; off >>= 1) q += __shfl_xor_sync(0xffffffffu, q, off);
    float rs = rsqrtf(q * (1.f/128.f) + EPSX);
    float4 g4 = *(const float4*)(gamma + lane*4);
    float4 b4 = *(const float4*)(beta  + lane*4);
    float4 o;
    o.x = d0*rs*g4.x + b4.x;
    o.y = d1*rs*g4.y + b4.y;
    o.z = d2*rs*g4.z + b4.z;
    o.w = d3*rs*g4.w + b4.w;
    *(float4*)(dst + lane*4) = o;
}

struct SmemAttn {
    float uacc[32][KSLOT][HH];   // 48 KB per-warp update partials
    float wsum[32][KSLOT];       // per-warp attn-weight sums
};
struct SmemGru {
    float gi[KSLOT][3*HH];
    float gh[KSLOT][3*HH];
    float h1[KSLOT][2*HH];
};
struct IterSmem {
    union { SmemAttn a; SmemGru g; } u;
    float s_prev[KSLOT][HH];
    float s_ln  [KSLOT][HH];
    float q_s   [KSLOT][HH];
    float qp    [KSLOT][HH];     // q' = q@Wk (scale folded)
    float upr   [KSLOT][HH];     // u' = sum_n w*in
    float u_s   [KSLOT][HH];     // updates
    float s_new [KSLOT][HH];
    float m_ln  [KSLOT][HH];
    float qbk[KSLOT];            // q·bk
    float wsr[KSLOT];            // sum_n w
};

__global__ void __launch_bounds__(1024)
iter_kernel(const float* __restrict__ Wq,  const float* __restrict__ bq,
            const float* __restrict__ Wk,  const float* __restrict__ bk,
            const float* __restrict__ Wv,  const float* __restrict__ bv,
            const float* __restrict__ gs,  const float* __restrict__ bs,
            const float* __restrict__ Wih, const float* __restrict__ bih,
            const float* __restrict__ Whh, const float* __restrict__ bhh,
            const float* __restrict__ W1,  const float* __restrict__ b1,
            const float* __restrict__ W2,  const float* __restrict__ b2,
            const float* __restrict__ gm,  const float* __restrict__ bm,
            float* __restrict__ out_slots, float* __restrict__ out_attn,
            int writeSlots, int writeAttn)
{
    extern __shared__ __align__(16) char smem_raw[];
    IterSmem& S = *reinterpret_cast<IterSmem*>(smem_raw);

    const int b    = blockIdx.x;
    const int tid  = threadIdx.x;
    const int lane = tid & 31;
    const int warp = tid >> 5;

    if (tid < KSLOT*HH) S.s_prev[0][tid] = g_slots[b*KSLOT*HH + tid];
    __syncthreads();

    // --- LN(slots) ---
    if (warp < KSLOT) warp_ln_row(S.s_prev[warp], S.s_ln[warp], gs, bs, lane);
    __syncthreads();

    // --- q = s_ln @ Wq^T + bq, scale folded ---
    if (tid < HH) {
        const int j = tid;
        const float4* wr = (const float4*)(Wq + (size_t)j*HH);
        float d0 = 0.f, d1 = 0.f, d2 = 0.f;
        #pragma unroll 8
        for (int i = 0; i < HH/4; i++) {
            float4 w  = wr[i];
            float4 a0 = *(const float4*)&S.s_ln[0][i*4];
            float4 a1 = *(const float4*)&S.s_ln[1][i*4];
            float4 a2 = *(const float4*)&S.s_ln[2][i*4];
            d0 += w.x*a0.x + w.y*a0.y + w.z*a0.z + w.w*a0.w;
            d1 += w.x*a1.x + w.y*a1.y + w.z*a1.z + w.w*a1.w;
            d2 += w.x*a2.x + w.y*a2.y + w.z*a2.z + w.w*a2.w;
        }
        float bb = bq[j];
        S.q_s[0][j] = (d0 + bb) * SCALE;
        S.q_s[1][j] = (d1 + bb) * SCALE;
        S.q_s[2][j] = (d2 + bb) * SCALE;
    }
    __syncthreads();

    // --- q' = q @ Wk (column access, coalesced); qbk = q·bk ---
    if (tid < KSLOT*HH) {
        const int s = tid >> 7, i = tid & 127;
        float acc = 0.f;
        #pragma unroll 8
        for (int j = 0; j < HH; j++)
            acc = fmaf(S.q_s[s][j], Wk[j*HH + i], acc);
        S.qp[s][i] = acc;
    } else if (tid < KSLOT*HH + KSLOT) {
        const int s = tid - KSLOT*HH;
        float acc = 0.f;
        const float4* bk4 = (const float4*)bk;
        #pragma unroll 8
        for (int i = 0; i < HH/4; i++) {
            float4 bv4 = bk4[i];
            float4 qv  = *(const float4*)&S.q_s[s][i*4];
            acc += qv.x*bv4.x + qv.y*bv4.y + qv.z*bv4.z + qv.w*bv4.w;
        }
        S.qbk[s] = acc;
    }
    __syncthreads();

    // --- Fused stream: warp per token; dots -> softmax -> accumulate w*in ---
    {
        float4 qp0 = *(const float4*)&S.qp[0][lane*4];
        float4 qp1 = *(const float4*)&S.qp[1][lane*4];
        float4 qp2 = *(const float4*)&S.qp[2][lane*4];
        const float qb0 = S.qbk[0], qb1 = S.qbk[1], qb2 = S.qbk[2];
        float4 ac0 = make_float4(0,0,0,0);
        float4 ac1 = make_float4(0,0,0,0);
        float4 ac2 = make_float4(0,0,0,0);
        float ws0 = 0.f, ws1 = 0.f, ws2 = 0.f;

        const float* inb = g_inputs + (size_t)b * NN * HH;
        for (int n = warp; n < NN; n += 32) {
            float4 x = *(const float4*)(inb + (size_t)n * HH + lane*4);
            float p0 = qp0.x*x.x + qp0.y*x.y + qp0.z*x.z + qp0.w*x.w;
            float p1 = qp1.x*x.x + qp1.y*x.y + qp1.z*x.z + qp1.w*x.w;
            float p2 = qp2.x*x.x + qp2.y*x.y + qp2.z*x.z + qp2.w*x.w;
            #pragma unroll
            for (int off = 16; off > 0; off >>= 1) {
                p0 += __shfl_xor_sync(0xffffffffu, p0, off);
                p1 += __shfl_xor_sync(0xffffffffu, p1, off);
                p2 += __shfl_xor_sync(0xffffffffu, p2, off);
            }
            float d0 = p0 + qb0, d1 = p1 + qb1, d2 = p2 + qb2;
            float mx = fmaxf(d0, fmaxf(d1, d2));
            float e0 = expf(d0-mx), e1 = expf(d1-mx), e2 = expf(d2-mx);
            float inv = 1.f / (e0 + e1 + e2);
            float w0 = e0*inv, w1 = e1*inv, w2 = e2*inv;
            if (writeAttn && lane < KSLOT) {
                float wv = (lane == 0) ? w0 : (lane == 1) ? w1 : w2;
                out_attn[((size_t)b*KSLOT + lane)*NN + n] = wv;
            }
            ac0.x = fmaf(w0, x.x, ac0.x); ac0.y = fmaf(w0, x.y, ac0.y);
            ac0.z = fmaf(w0, x.z, ac0.z); ac0.w = fmaf(w0, x.w, ac0.w);
            ac1.x = fmaf(w1, x.x, ac1.x); ac1.y = fmaf(w1, x.y, ac1.y);
            ac1.z = fmaf(w1, x.z, ac1.z); ac1.w = fmaf(w1, x.w, ac1.w);
            ac2.x = fmaf(w2, x.x, ac2.x); ac2.y = fmaf(w2, x.y, ac2.y);
            ac2.z = fmaf(w2, x.z, ac2.z); ac2.w = fmaf(w2, x.w, ac2.w);
            ws0 += w0; ws1 += w1; ws2 += w2;
        }
        *(float4*)&S.u.a.uacc[warp][0][lane*4] = ac0;
        *(float4*)&S.u.a.uacc[warp][1][lane*4] = ac1;
        *(float4*)&S.u.a.uacc[warp][2][lane*4] = ac2;
        if (lane == 0) {
            S.u.a.wsum[warp][0] = ws0;
            S.u.a.wsum[warp][1] = ws1;
            S.u.a.wsum[warp][2] = ws2;
        }
    }
    __syncthreads();

    // --- cross-warp reduce: u' and W sums ---
    if (tid < KSLOT*HH) {
        const int s = tid >> 7, i = tid & 127;
        float a = 0.f;
        #pragma unroll
        for (int w = 0; w < 32; w++) a += S.u.a.uacc[w][s][i];
        S.upr[s][i] = a;
    }
    if (tid < KSLOT) {
        float a = 0.f;
        #pragma unroll
        for (int w = 0; w < 32; w++) a += S.u.a.wsum[w][tid];
        S.wsr[tid] = a;
    }
    __syncthreads();

    // --- updates = u' @ Wv^T + W·bv ---
    if (tid < KSLOT*HH) {
        const int s = tid >> 7, j = tid & 127;
        const float4* wr = (const float4*)(Wv + (size_t)j*HH);
        float acc = 0.f;
        #pragma unroll 8
        for (int i = 0; i < HH/4; i++) {
            float4 w = wr[i];
            float4 x = *(const float4*)&S.upr[s][i*4];
            acc += w.x*x.x + w.y*x.y + w.z*x.z + w.w*x.w;
        }
        S.u_s[s][j] = acc + S.wsr[s] * bv[j];
    }
    __syncthreads();

    // --- GRU gates (union reused: uacc dead, u_s holds result) ---
    if (tid < 3*HH) {
        const int o = tid;
        {
            const float4* wr = (const float4*)(Wih + (size_t)o*HH);
            float d0=0,d1=0,d2=0;
            #pragma unroll 4
            for (int i = 0; i < HH/4; i++) {
                float4 w  = wr[i];
                float4 x0 = *(const float4*)&S.u_s[0][i*4];
                float4 x1 = *(const float4*)&S.u_s[1][i*4];
                float4 x2 = *(const float4*)&S.u_s[2][i*4];
                d0 += w.x*x0.x + w.y*x0.y + w.z*x0.z + w.w*x0.w;
                d1 += w.x*x1.x + w.y*x1.y + w.z*x1.z + w.w*x1.w;
                d2 += w.x*x2.x + w.y*x2.y + w.z*x2.z + w.w*x2.w;
            }
            float bb = bih[o];
            S.u.g.gi[0][o] = d0+bb; S.u.g.gi[1][o] = d1+bb; S.u.g.gi[2][o] = d2+bb;
        }
        {
            const float4* wr = (const float4*)(Whh + (size_t)o*HH);
            float d0=0,d1=0,d2=0;
            #pragma unroll 4
            for (int i = 0; i < HH/4; i++) {
                float4 w  = wr[i];
                float4 x0 = *(const float4*)&S.s_prev[0][i*4];
                float4 x1 = *(const float4*)&S.s_prev[1][i*4];
                float4 x2 = *(const float4*)&S.s_prev[2][i*4];
                d0 += w.x*x0.x + w.y*x0.y + w.z*x0.z + w.w*x0.w;
                d1 += w.x*x1.x + w.y*x1.y + w.z*x1.z + w.w*x1.w;
                d2 += w.x*x2.x + w.y*x2.y + w.z*x2.z + w.w*x2.w;
            }
            float bb = bhh[o];
            S.u.g.gh[0][o] = d0+bb; S.u.g.gh[1][o] = d1+bb; S.u.g.gh[2][o] = d2+bb;
        }
    }
    __syncthreads();
    if (tid < KSLOT*HH) {
        int s = tid >> 7, j = tid & 127;
        float ir = S.u.g.gi[s][j], iz = S.u.g.gi[s][HH+j], inn = S.u.g.gi[s][2*HH+j];
        float hr = S.u.g.gh[s][j], hz = S.u.g.gh[s][HH+j], hn  = S.u.g.gh[s][2*HH+j];
        float r  = 1.f / (1.f + expf(-(ir+hr)));
        float z  = 1.f / (1.f + expf(-(iz+hz)));
        float nn = tanhf(inn + r*hn);
        S.s_new[s][j] = (1.f - z)*nn + z*S.s_prev[s][j];
    }
    __syncthreads();

    // --- MLP with residual ---
    if (warp < KSLOT) warp_ln_row(S.s_new[warp], S.m_ln[warp], gm, bm, lane);
    __syncthreads();
    if (tid < 2*HH) {
        const int jr = tid;
        const float4* wr = (const float4*)(W1 + (size_t)jr*HH);
        float d0=0,d1=0,d2=0;
        #pragma unroll 4
        for (int i = 0; i < HH/4; i++) {
            float4 w  = wr[i];
            float4 x0 = *(const float4*)&S.m_ln[0][i*4];
            float4 x1 = *(const float4*)&S.m_ln[1][i*4];
            float4 x2 = *(const float4*)&S.m_ln[2][i*4];
            d0 += w.x*x0.x + w.y*x0.y + w.z*x0.z + w.w*x0.w;
            d1 += w.x*x1.x + w.y*x1.y + w.z*x1.z + w.w*x1.w;
            d2 += w.x*x2.x + w.y*x2.y + w.z*x2.z + w.w*x2.w;
        }
        float bb = b1[jr];
        S.u.g.h1[0][jr] = geluf(d0+bb);
        S.u.g.h1[1][jr] = geluf(d1+bb);
        S.u.g.h1[2][jr] = geluf(d2+bb);
    }
    __syncthreads();
    if (tid < HH) {
        const int j = tid;
        const float4* wr = (const float4*)(W2 + (size_t)j*2*HH);
        float d0=0,d1=0,d2=0;
        #pragma unroll 4
        for (int i = 0; i < (2*HH)/4; i++) {
            float4 w  = wr[i];
            float4 x0 = *(const float4*)&S.u.g.h1[0][i*4];
            float4 x1 = *(const float4*)&S.u.g.h1[1][i*4];
            float4 x2 = *(const float4*)&S.u.g.h1[2][i*4];
            d0 += w.x*x0.x + w.y*x0.y + w.z*x0.z + w.w*x0.w;
            d1 += w.x*x1.x + w.y*x1.y + w.z*x1.z + w.w*x1.w;
            d2 += w.x*x2.x + w.y*x2.y + w.z*x2.z + w.w*x2.w;
        }
        float bb = b2[j];
        float f0 = S.s_new[0][j] + d0 + bb;
        float f1 = S.s_new[1][j] + d1 + bb;
        float f2 = S.s_new[2][j] + d2 + bb;
        g_slots[b*KSLOT*HH + 0*HH + j] = f0;
        g_slots[b*KSLOT*HH + 1*HH + j] = f1;
        g_slots[b*KSLOT*HH + 2*HH + j] = f2;
        if (writeSlots) {
            out_slots[(size_t)b*KSLOT*HH + 0*HH + j] = f0;
            out_slots[(size_t)b*KSLOT*HH + 1*HH + j] = f1;
            out_slots[(size_t)b*KSLOT*HH + 2*HH + j] = f2;
        }
    }
}

// ---------------------------------------------------------------------------
// Launch
// ---------------------------------------------------------------------------
extern "C" void kernel_launch(void* const* d_in, const int* in_sizes, int n_in,
                              void* d_out, int out_size)
{
    const float* patch = (const float*)d_in[0];
    const float* noise = (const float*)d_in[1];
    const float* smu   = (const float*)d_in[2];
    const float* slsig = (const float*)d_in[3];
    const float* Wp    = (const float*)d_in[4];
    const float* bp    = (const float*)d_in[5];
    const float* g_in  = (const float*)d_in[6];
    const float* b_in  = (const float*)d_in[7];
    const float* Wq    = (const float*)d_in[8];
    const float* bq    = (const float*)d_in[9];
    const float* Wk    = (const float*)d_in[10];
    const float* bk    = (const float*)d_in[11];
    const float* Wv    = (const float*)d_in[12];
    const float* bv    = (const float*)d_in[13];
    const float* Wih   = (const float*)d_in[14];
    const float* bih   = (const float*)d_in[15];
    const float* Whh   = (const float*)d_in[16];
    const float* bhh   = (const float*)d_in[17];
    const float* gs    = (const float*)d_in[18];
    const float* bs    = (const float*)d_in[19];
    const float* W1    = (const float*)d_in[20];
    const float* b1    = (const float*)d_in[21];
    const float* W2    = (const float*)d_in[22];
    const float* b2    = (const float*)d_in[23];
    const float* gm    = (const float*)d_in[24];
    const float* bm    = (const float*)d_in[25];

    float *pWpT, *pIn;
    cudaGetSymbolAddress((void**)&pWpT, g_WpT);
    cudaGetSymbolAddress((void**)&pIn,  g_inputs);

    const int slotsElems = BB*KSLOT*HH;
    const int attnElems  = BB*KSLOT*NN;
    const int writeSlots = (out_size >= slotsElems) ? 1 : 0;
    const int writeAttn  = (out_size >= slotsElems + attnElems) ? 1 : 0;
    float* outSlots = (float*)d_out;
    float* outAttn  = (float*)d_out + slotsElems;

    const int iterSmem = (int)sizeof(IterSmem);
    static int attrSet = 0;
    if (!attrSet) {
        cudaFuncSetAttribute(iter_kernel,
                             cudaFuncAttributeMaxDynamicSharedMemorySize, iterSmem);
        attrSet = 1;
    }

    // 1) transpose Wp + init slots
    prep_kernel<<<192, 256>>>(Wp, noise, smu, slsig);

    // 2) inputs = LN(X @ Wp^T + bp)   — the only big GEMM left
    gemm_ln<DIN><<<MTOT/128, 256>>>(patch, pWpT, bp, g_in, b_in, pIn);

    // 3) 3 slot-attention iterations (k/v algebraically eliminated)
    for (int it = 0; it < NITER; it++) {
        int last = (it == NITER - 1);
        iter_kernel<<<BB, 1024, iterSmem>>>(Wq, bq, Wk, bk, Wv, bv,
                                            gs, bs, Wih, bih, Whh, bhh,
                                            W1, b1, W2, b2, gm, bm,
                                            outSlots, outAttn,
                                            last ? writeSlots : 0,
                                            last ? writeAttn  : 0);
    }
}

// round 16
// speedup vs baseline: 2.0248x; 1.0274x over previous
#include <cuda_runtime.h>
#include <math.h>

// Problem constants (fixed bench shapes)
#define BB    128
#define NN    1024
#define DIN   192
#define HH    128
#define KSLOT 3
#define NITER 3
#define EPSX  1e-5f
#define MTOT  (BB*NN)              // 131072 token rows
#define SCALE 0.08838834764831845f // 1/sqrt(128)

#define TILE   128                 // tokens per smem tile
#define TILES  (NN/TILE)           // 8
#define TSTR   132                 // padded row stride (floats), 528B (16B-aligned)
#define TILE_BYTES (TILE*TSTR*4)   // 67584
#define USTR   400                 // uacc warp stride (floats): 16B-aligned, bank-shifted

typedef unsigned int uint32;
typedef unsigned long long ull;

// ---------------------------------------------------------------------------
// Scratch (device globals: allocation-free rule)
// ---------------------------------------------------------------------------
__device__ float g_WpT[DIN*HH];
__device__ float g_inputs[(size_t)MTOT*HH];  // 67 MB
__device__ float g_slots[BB*KSLOT*HH];

// f32x2 helpers ------------------------------------------------------------
__device__ __forceinline__ ull splat2(float a) {
    ull r; asm("mov.b64 %0, {%1, %1};" : "=l"(r) : "f"(a)); return r;
}
__device__ __forceinline__ void fma2(ull& d, ull a, ull b) {
    asm("fma.rn.f32x2 %0, %1, %2, %0;" : "+l"(d) : "l"(a), "l"(b));
}
__device__ __forceinline__ float2 unpack2(ull v) {
    float2 r; asm("mov.b64 {%0, %1}, %2;" : "=f"(r.x), "=f"(r.y) : "l"(v)); return r;
}
__device__ __forceinline__ uint32 smem_u32(const void* p) {
    uint32 a;
    asm("{ .reg .u64 t; cvta.to.shared.u64 t, %1; cvt.u32.u64 %0, t; }"
        : "=r"(a) : "l"(p));
    return a;
}

// ---------------------------------------------------------------------------
// Prep: transpose Wp for coalesced GEMM B-loads; init slots
// ---------------------------------------------------------------------------
__global__ void prep_kernel(const float* __restrict__ Wp,
                            const float* __restrict__ noise,
                            const float* __restrict__ slot_mu,
                            const float* __restrict__ slot_lsig)
{
    int i = blockIdx.x * blockDim.x + threadIdx.x;
    if (i < HH*DIN) {                 // Wp: [128][192] -> WpT[192][128]
        int r = i / DIN, c = i % DIN;
        g_WpT[c*HH + r] = Wp[i];
    }
    if (i < BB*KSLOT*HH) {            // slots = mu + exp(log_sigma)*noise
        int kh = i % (KSLOT*HH);
        g_slots[i] = slot_mu[kh] + expf(slot_lsig[kh]) * noise[i];
    }
}

// ---------------------------------------------------------------------------
// SGEMM (R8, proven): double-buffered smem, one sync per k-tile, f32x2 FMA,
// LayerNorm epilogue. 128x128 per block, 256 threads.
// ---------------------------------------------------------------------------
template<int KDIM>
__global__ void __launch_bounds__(256)
gemm_ln(const float* __restrict__ A, const float* __restrict__ Bm,
        const float* __restrict__ bias, const float* __restrict__ gamma,
        const float* __restrict__ beta, float* __restrict__ out)
{
    __shared__ __align__(16) float As[2][8][132];
    __shared__ __align__(16) float Bs[2][8][128];
    __shared__ float psum[16][129];
    __shared__ float psq [16][129];
    __shared__ float smu[128], srs[128];

    const int tid = threadIdx.x;
    const int tx = tid & 15, ty = tid >> 4;
    const int m0 = blockIdx.x * 128;

    const int aRow = tid >> 1;
    const int aCol = (tid & 1) * 4;
    const int bRow = tid >> 5;
    const int bCol = (tid & 31) * 4;

    const float* Ab = A + (size_t)m0 * KDIM;
    const int NT = KDIM / 8;

    ull acc2[8][4];
    #pragma unroll
    for (int i = 0; i < 8; i++)
        #pragma unroll
        for (int j = 0; j < 4; j++) acc2[i][j] = 0ull;

    {
        float4 a4 = *(const float4*)(Ab + (size_t)aRow * KDIM + aCol);
        As[0][aCol+0][aRow] = a4.x;
        As[0][aCol+1][aRow] = a4.y;
        As[0][aCol+2][aRow] = a4.z;
        As[0][aCol+3][aRow] = a4.w;
        *(float4*)&Bs[0][bRow][bCol] =
            *(const float4*)(Bm + (size_t)bRow * HH + bCol);
    }
    __syncthreads();

    for (int t = 0; t < NT; t++) {
        const int buf = t & 1;
        float4 na, nb;
        if (t + 1 < NT) {
            na = *(const float4*)(Ab + (size_t)aRow * KDIM + ((t+1)*8 + aCol));
            nb = *(const float4*)(Bm + (size_t)((t+1)*8 + bRow) * HH + bCol);
        }
        #pragma unroll
        for (int kk = 0; kk < 8; kk++) {
            float a[8];
            *(float4*)&a[0] = *(const float4*)&As[buf][kk][ty*8];
            *(float4*)&a[4] = *(const float4*)&As[buf][kk][ty*8+4];
            ull b2[4];
            const ull* bp = (const ull*)&Bs[buf][kk][tx*8];
            b2[0] = bp[0]; b2[1] = bp[1]; b2[2] = bp[2]; b2[3] = bp[3];
            #pragma unroll
            for (int i = 0; i < 8; i++) {
                ull av = splat2(a[i]);
                fma2(acc2[i][0], av, b2[0]);
                fma2(acc2[i][1], av, b2[1]);
                fma2(acc2[i][2], av, b2[2]);
                fma2(acc2[i][3], av, b2[3]);
            }
        }
        if (t + 1 < NT) {
            const int nbuf = buf ^ 1;
            As[nbuf][aCol+0][aRow] = na.x;
            As[nbuf][aCol+1][aRow] = na.y;
            As[nbuf][aCol+2][aRow] = na.z;
            As[nbuf][aCol+3][aRow] = na.w;
            *(float4*)&Bs[nbuf][bRow][bCol] = nb;
            __syncthreads();
        }
    }

    float accf[8][8];
    float bj[8];
    #pragma unroll
    for (int j = 0; j < 8; j++) bj[j] = bias[tx*8 + j];
    #pragma unroll
    for (int i = 0; i < 8; i++)
        #pragma unroll
        for (int jp = 0; jp < 4; jp++) {
            float2 f = unpack2(acc2[i][jp]);
            accf[i][2*jp]   = f.x + bj[2*jp];
            accf[i][2*jp+1] = f.y + bj[2*jp+1];
        }

    __syncthreads();
    #pragma unroll
    for (int i = 0; i < 8; i++) {
        int row = ty*8 + i;
        float s = 0.f, q = 0.f;
        #pragma unroll
        for (int j = 0; j < 8; j++) { s += accf[i][j]; q += accf[i][j]*accf[i][j]; }
        psum[tx][row] = s;
        psq [tx][row] = q;
    }
    __syncthreads();
    if (tid < 128) {
        float s = 0.f, q = 0.f;
        #pragma unroll
        for (int t = 0; t < 16; t++) { s += psum[t][tid]; q += psq[t][tid]; }
        float mu  = s * (1.f/128.f);
        float var = q * (1.f/128.f) - mu*mu;
        smu[tid] = mu;
        srs[tid] = rsqrtf(var + EPSX);
    }
    __syncthreads();
    float gj[8], b2j[8];
    #pragma unroll
    for (int j = 0; j < 8; j++) { gj[j] = gamma[tx*8+j]; b2j[j] = beta[tx*8+j]; }
    #pragma unroll
    for (int i = 0; i < 8; i++) {
        int row = ty*8 + i;
        float mu = smu[row], rs = srs[row];
        float o[8];
        #pragma unroll
        for (int j = 0; j < 8; j++) o[j] = (accf[i][j]-mu)*rs*gj[j] + b2j[j];
        float4* dst = (float4*)(out + (size_t)(m0+row)*HH + tx*8);
        dst[0] = make_float4(o[0], o[1], o[2], o[3]);
        dst[1] = make_float4(o[4], o[5], o[6], o[7]);
    }
}

// ---------------------------------------------------------------------------
// Fused per-iteration kernel v3. One block per batch, 1024 threads.
// k/v algebraically eliminated (R14). Streaming phase: cp.async
// double-buffered 128-token smem tiles; dots thread-per-token from smem
// (no shuffles); accumulation warp-per-token from smem.
// ---------------------------------------------------------------------------
__device__ __forceinline__ float geluf(float x) {
    return 0.5f * x * (1.f + erff(x * 0.70710678118654752f));
}

__device__ __forceinline__ void warp_ln_row(const float* __restrict__ src,
                                            float* __restrict__ dst,
                                            const float* __restrict__ gamma,
                                            const float* __restrict__ beta,
                                            int lane)
{
    float4 xv = *(const float4*)(src + lane*4);
    float s = xv.x + xv.y + xv.z + xv.w;
    #pragma unroll
    for (int off = 16; off > 0; off >>= 1) s += __shfl_xor_sync(0xffffffffu, s, off);
    float mu = s * (1.f/128.f);
    float d0 = xv.x-mu, d1 = xv.y-mu, d2 = xv.z-mu, d3 = xv.w-mu;
    float q = d0*d0 + d1*d1 + d2*d2 + d3*d3;
    #pragma unroll
    for (int off = 16; off > 0; off >>= 1) q += __shfl_xor_sync(0xffffffffu, q, off);
    float rs = rsqrtf(q * (1.f/128.f) + EPSX);
    float4 g4 = *(const float4*)(gamma + lane*4);
    float4 b4 = *(const float4*)(beta  + lane*4);
    float4 o;
    o.x = d0*rs*g4.x + b4.x;
    o.y = d1*rs*g4.y + b4.y;
    o.z = d2*rs*g4.z + b4.z;
    o.w = d3*rs*g4.w + b4.w;
    *(float4*)(dst + lane*4) = o;
}

struct IterSmem {
    union {
        float tile[2][TILE][TSTR];          // 135168 B streaming buffers
        struct {
            float uacc[32*USTR];            // w*USTR + s*128 + i (16B-aligned)
            float wsum[32][KSLOT];
            float gi[KSLOT][3*HH];
            float gh[KSLOT][3*HH];
            float h1[KSLOT][2*HH];
        } tail;
    } u;
    float w[KSLOT][TILE];        // attn weights of current tile
    float s_prev[KSLOT][HH];
    float s_ln  [KSLOT][HH];
    float q_s   [KSLOT][HH];
    float qp    [KSLOT][HH];     // q' = q@Wk (scale folded)
    float upr   [KSLOT][HH];     // u' = sum_n w*in
    float u_s   [KSLOT][HH];     // updates
    float s_new [KSLOT][HH];
    float m_ln  [KSLOT][HH];
    float qbk[KSLOT];            // q·bk
    float wsr[KSLOT];            // sum_n w
};

__device__ __forceinline__ void issue_tile_cp(uint32 tileBase, int bb,
                                              const float4* gsrc0, int tt, int tid)
{
    #pragma unroll
    for (int k = 0; k < 4; k++) {
        int g = tid + k*1024;
        int tok = g >> 5, c4 = g & 31;
        uint32 daddr = tileBase + (uint32)bb*TILE_BYTES + tok*(TSTR*4) + c4*16;
        const float4* src = gsrc0 + (size_t)tt*4096 + g;
        asm volatile("cp.async.cg.shared.global [%0], [%1], 16;"
                     :: "r"(daddr), "l"((const void*)src) : "memory");
    }
    asm volatile("cp.async.commit_group;" ::: "memory");
}

__global__ void __launch_bounds__(1024)
iter_kernel(const float* __restrict__ Wq,  const float* __restrict__ bq,
            const float* __restrict__ Wk,  const float* __restrict__ bk,
            const float* __restrict__ Wv,  const float* __restrict__ bv,
            const float* __restrict__ gs,  const float* __restrict__ bs,
            const float* __restrict__ Wih, const float* __restrict__ bih,
            const float* __restrict__ Whh, const float* __restrict__ bhh,
            const float* __restrict__ W1,  const float* __restrict__ b1,
            const float* __restrict__ W2,  const float* __restrict__ b2,
            const float* __restrict__ gm,  const float* __restrict__ bm,
            float* __restrict__ out_slots, float* __restrict__ out_attn,
            int writeSlots, int writeAttn)
{
    extern __shared__ __align__(16) char smem_raw[];
    IterSmem& S = *reinterpret_cast<IterSmem*>(smem_raw);

    const int b    = blockIdx.x;
    const int tid  = threadIdx.x;
    const int lane = tid & 31;
    const int warp = tid >> 5;

    const float*  inb   = g_inputs + (size_t)b * NN * HH;
    const float4* gsrc0 = (const float4*)inb;
    const uint32  tileBase = smem_u32(&S.u.tile[0][0][0]);

    // kick off tile 0 immediately (overlaps with all the small GEMVs below)
    issue_tile_cp(tileBase, 0, gsrc0, 0, tid);

    if (tid < KSLOT*HH) S.s_prev[0][tid] = g_slots[b*KSLOT*HH + tid];
    __syncthreads();

    // --- LN(slots) ---
    if (warp < KSLOT) warp_ln_row(S.s_prev[warp], S.s_ln[warp], gs, bs, lane);
    __syncthreads();

    // --- q = s_ln @ Wq^T + bq, scale folded ---
    if (tid < HH) {
        const int j = tid;
        const float4* wr = (const float4*)(Wq + (size_t)j*HH);
        float d0 = 0.f, d1 = 0.f, d2 = 0.f;
        #pragma unroll 8
        for (int i = 0; i < HH/4; i++) {
            float4 w  = wr[i];
            float4 a0 = *(const float4*)&S.s_ln[0][i*4];
            float4 a1 = *(const float4*)&S.s_ln[1][i*4];
            float4 a2 = *(const float4*)&S.s_ln[2][i*4];
            d0 += w.x*a0.x + w.y*a0.y + w.z*a0.z + w.w*a0.w;
            d1 += w.x*a1.x + w.y*a1.y + w.z*a1.z + w.w*a1.w;
            d2 += w.x*a2.x + w.y*a2.y + w.z*a2.z + w.w*a2.w;
        }
        float bb = bq[j];
        S.q_s[0][j] = (d0 + bb) * SCALE;
        S.q_s[1][j] = (d1 + bb) * SCALE;
        S.q_s[2][j] = (d2 + bb) * SCALE;
    }
    __syncthreads();

    // --- q' = q @ Wk (column access); qbk = q·bk ---
    if (tid < KSLOT*HH) {
        const int s = tid >> 7, i = tid & 127;
        float acc = 0.f;
        #pragma unroll 8
        for (int j = 0; j < HH; j++)
            acc = fmaf(S.q_s[s][j], Wk[j*HH + i], acc);
        S.qp[s][i] = acc;
    } else if (tid < KSLOT*HH + KSLOT) {
        const int s = tid - KSLOT*HH;
        float acc = 0.f;
        const float4* bk4 = (const float4*)bk;
        #pragma unroll 8
        for (int i = 0; i < HH/4; i++) {
            float4 bv4 = bk4[i];
            float4 qv  = *(const float4*)&S.q_s[s][i*4];
            acc += qv.x*bv4.x + qv.y*bv4.y + qv.z*bv4.z + qv.w*bv4.w;
        }
        S.qbk[s] = acc;
    }
    __syncthreads();

    // --- Streaming over 8 double-buffered smem tiles ---
    float4 ac0 = make_float4(0,0,0,0);
    float4 ac1 = make_float4(0,0,0,0);
    float4 ac2 = make_float4(0,0,0,0);
    float ws0 = 0.f, ws1 = 0.f, ws2 = 0.f;

    for (int t = 0; t < TILES; t++) {
        const int buf = t & 1;
        asm volatile("cp.async.wait_group 0;" ::: "memory");
        __syncthreads();           // all threads' copies of tile t visible

        // prefetch tile t+1 into the other buffer (freed by accum of t-1)
        if (t + 1 < TILES)
            issue_tile_cp(tileBase, buf ^ 1, gsrc0, t + 1, tid);

        // --- dot + softmax: thread-per-token, no shuffles ---
        if (tid < TILE) {
            const float* row = &S.u.tile[buf][tid][0];
            float d0 = S.qbk[0], d1 = S.qbk[1], d2 = S.qbk[2];
            #pragma unroll 8
            for (int i = 0; i < HH/4; i++) {
                float4 x  = *(const float4*)(row + i*4);
                float4 p0 = *(const float4*)&S.qp[0][i*4];
                float4 p1 = *(const float4*)&S.qp[1][i*4];
                float4 p2 = *(const float4*)&S.qp[2][i*4];
                d0 += p0.x*x.x + p0.y*x.y + p0.z*x.z + p0.w*x.w;
                d1 += p1.x*x.x + p1.y*x.y + p1.z*x.z + p1.w*x.w;
                d2 += p2.x*x.x + p2.y*x.y + p2.z*x.z + p2.w*x.w;
            }
            float mx = fmaxf(d0, fmaxf(d1, d2));
            float e0 = expf(d0-mx), e1 = expf(d1-mx), e2 = expf(d2-mx);
            float inv = 1.f / (e0 + e1 + e2);
            float w0 = e0*inv, w1 = e1*inv, w2 = e2*inv;
            S.w[0][tid] = w0;
            S.w[1][tid] = w1;
            S.w[2][tid] = w2;
            if (writeAttn) {
                int n = t*TILE + tid;
                float* ob = out_attn + (size_t)b * KSLOT * NN + n;
                ob[0]    = w0;
                ob[NN]   = w1;
                ob[2*NN] = w2;
            }
        }
        __syncthreads();

        // --- accumulate u' += w * x : warp-per-token (4 per warp) ---
        #pragma unroll
        for (int j = 0; j < 4; j++) {
            int n = warp + 32*j;
            float w0 = S.w[0][n], w1 = S.w[1][n], w2 = S.w[2][n];
            float4 x = *(const float4*)&S.u.tile[buf][n][lane*4];
            ac0.x = fmaf(w0, x.x, ac0.x); ac0.y = fmaf(w0, x.y, ac0.y);
            ac0.z = fmaf(w0, x.z, ac0.z); ac0.w = fmaf(w0, x.w, ac0.w);
            ac1.x = fmaf(w1, x.x, ac1.x); ac1.y = fmaf(w1, x.y, ac1.y);
            ac1.z = fmaf(w1, x.z, ac1.z); ac1.w = fmaf(w1, x.w, ac1.w);
            ac2.x = fmaf(w2, x.x, ac2.x); ac2.y = fmaf(w2, x.y, ac2.y);
            ac2.z = fmaf(w2, x.z, ac2.z); ac2.w = fmaf(w2, x.w, ac2.w);
            ws0 += w0; ws1 += w1; ws2 += w2;
        }
    }
    __syncthreads();   // tiles dead; tail union region becomes live

    // --- per-warp partials -> smem (USTR=400: 16B-aligned stride) ---
    *(float4*)&S.u.tail.uacc[warp*USTR + 0*128 + lane*4] = ac0;
    *(float4*)&S.u.tail.uacc[warp*USTR + 1*128 + lane*4] = ac1;
    *(float4*)&S.u.tail.uacc[warp*USTR + 2*128 + lane*4] = ac2;
    if (lane == 0) {
        S.u.tail.wsum[warp][0] = ws0;
        S.u.tail.wsum[warp][1] = ws1;
        S.u.tail.wsum[warp][2] = ws2;
    }
    __syncthreads();

    // --- cross-warp reduce ---
    if (tid < KSLOT*HH) {
        const int s = tid >> 7, i = tid & 127;
        float a = 0.f;
        #pragma unroll
        for (int w = 0; w < 32; w++) a += S.u.tail.uacc[w*USTR + s*128 + i];
        S.upr[s][i] = a;
    }
    if (tid < KSLOT) {
        float a = 0.f;
        #pragma unroll
        for (int w = 0; w < 32; w++) a += S.u.tail.wsum[w][tid];
        S.wsr[tid] = a;
    }
    __syncthreads();

    // --- updates = u' @ Wv^T + W·bv ---
    if (tid < KSLOT*HH) {
        const int s = tid >> 7, j = tid & 127;
        const float4* wr = (const float4*)(Wv + (size_t)j*HH);
        float acc = 0.f;
        #pragma unroll 8
        for (int i = 0; i < HH/4; i++) {
            float4 w = wr[i];
            float4 x = *(const float4*)&S.upr[s][i*4];
            acc += w.x*x.x + w.y*x.y + w.z*x.z + w.w*x.w;
        }
        S.u_s[s][j] = acc + S.wsr[s] * bv[j];
    }
    __syncthreads();

    // --- GRU gates ---
    if (tid < 3*HH) {
        const int o = tid;
        {
            const float4* wr = (const float4*)(Wih + (size_t)o*HH);
            float d0=0,d1=0,d2=0;
            #pragma unroll 4
            for (int i = 0; i < HH/4; i++) {
                float4 w  = wr[i];
                float4 x0 = *(const float4*)&S.u_s[0][i*4];
                float4 x1 = *(const float4*)&S.u_s[1][i*4];
                float4 x2 = *(const float4*)&S.u_s[2][i*4];
                d0 += w.x*x0.x + w.y*x0.y + w.z*x0.z + w.w*x0.w;
                d1 += w.x*x1.x + w.y*x1.y + w.z*x1.z + w.w*x1.w;
                d2 += w.x*x2.x + w.y*x2.y + w.z*x2.z + w.w*x2.w;
            }
            float bb = bih[o];
            S.u.tail.gi[0][o] = d0+bb; S.u.tail.gi[1][o] = d1+bb; S.u.tail.gi[2][o] = d2+bb;
        }
        {
            const float4* wr = (const float4*)(Whh + (size_t)o*HH);
            float d0=0,d1=0,d2=0;
            #pragma unroll 4
            for (int i = 0; i < HH/4; i++) {
                float4 w  = wr[i];
                float4 x0 = *(const float4*)&S.s_prev[0][i*4];
                float4 x1 = *(const float4*)&S.s_prev[1][i*4];
                float4 x2 = *(const float4*)&S.s_prev[2][i*4];
                d0 += w.x*x0.x + w.y*x0.y + w.z*x0.z + w.w*x0.w;
                d1 += w.x*x1.x + w.y*x1.y + w.z*x1.z + w.w*x1.w;
                d2 += w.x*x2.x + w.y*x2.y + w.z*x2.z + w.w*x2.w;
            }
            float bb = bhh[o];
            S.u.tail.gh[0][o] = d0+bb; S.u.tail.gh[1][o] = d1+bb; S.u.tail.gh[2][o] = d2+bb;
        }
    }
    __syncthreads();
    if (tid < KSLOT*HH) {
        int s = tid >> 7, j = tid & 127;
        float ir = S.u.tail.gi[s][j], iz = S.u.tail.gi[s][HH+j], inn = S.u.tail.gi[s][2*HH+j];
        float hr = S.u.tail.gh[s][j], hz = S.u.tail.gh[s][HH+j], hn  = S.u.tail.gh[s][2*HH+j];
        float r  = 1.f / (1.f + expf(-(ir+hr)));
        float z  = 1.f / (1.f + expf(-(iz+hz)));
        float nn = tanhf(inn + r*hn);
        S.s_new[s][j] = (1.f - z)*nn + z*S.s_prev[s][j];
    }
    __syncthreads();

    // --- MLP with residual ---
    if (warp < KSLOT) warp_ln_row(S.s_new[warp], S.m_ln[warp], gm, bm, lane);
    __syncthreads();
    if (tid < 2*HH) {
        const int jr = tid;
        const float4* wr = (const float4*)(W1 + (size_t)jr*HH);
        float d0=0,d1=0,d2=0;
        #pragma unroll 4
        for (int i = 0; i < HH/4; i++) {
            float4 w  = wr[i];
            float4 x0 = *(const float4*)&S.m_ln[0][i*4];
            float4 x1 = *(const float4*)&S.m_ln[1][i*4];
            float4 x2 = *(const float4*)&S.m_ln[2][i*4];
            d0 += w.x*x0.x + w.y*x0.y + w.z*x0.z + w.w*x0.w;
            d1 += w.x*x1.x + w.y*x1.y + w.z*x1.z + w.w*x1.w;
            d2 += w.x*x2.x + w.y*x2.y + w.z*x2.z + w.w*x2.w;
        }
        float bb = b1[jr];
        S.u.tail.h1[0][jr] = geluf(d0+bb);
        S.u.tail.h1[1][jr] = geluf(d1+bb);
        S.u.tail.h1[2][jr] = geluf(d2+bb);
    }
    __syncthreads();
    if (tid < HH) {
        const int j = tid;
        const float4* wr = (const float4*)(W2 + (size_t)j*2*HH);
        float d0=0,d1=0,d2=0;
        #pragma unroll 4
        for (int i = 0; i < (2*HH)/4; i++) {
            float4 w  = wr[i];
            float4 x0 = *(const float4*)&S.u.tail.h1[0][i*4];
            float4 x1 = *(const float4*)&S.u.tail.h1[1][i*4];
            float4 x2 = *(const float4*)&S.u.tail.h1[2][i*4];
            d0 += w.x*x0.x + w.y*x0.y + w.z*x0.z + w.w*x0.w;
            d1 += w.x*x1.x + w.y*x1.y + w.z*x1.z + w.w*x1.w;
            d2 += w.x*x2.x + w.y*x2.y + w.z*x2.z + w.w*x2.w;
        }
        float bb = b2[j];
        float f0 = S.s_new[0][j] + d0 + bb;
        float f1 = S.s_new[1][j] + d1 + bb;
        float f2 = S.s_new[2][j] + d2 + bb;
        g_slots[b*KSLOT*HH + 0*HH + j] = f0;
        g_slots[b*KSLOT*HH + 1*HH + j] = f1;
        g_slots[b*KSLOT*HH + 2*HH + j] = f2;
        if (writeSlots) {
            out_slots[(size_t)b*KSLOT*HH + 0*HH + j] = f0;
            out_slots[(size_t)b*KSLOT*HH + 1*HH + j] = f1;
            out_slots[(size_t)b*KSLOT*HH + 2*HH + j] = f2;
        }
    }
}

// ---------------------------------------------------------------------------
// Launch
// ---------------------------------------------------------------------------
extern "C" void kernel_launch(void* const* d_in, const int* in_sizes, int n_in,
                              void* d_out, int out_size)
{
    const float* patch = (const float*)d_in[0];
    const float* noise = (const float*)d_in[1];
    const float* smu   = (const float*)d_in[2];
    const float* slsig = (const float*)d_in[3];
    const float* Wp    = (const float*)d_in[4];
    const float* bp    = (const float*)d_in[5];
    const float* g_in  = (const float*)d_in[6];
    const float* b_in  = (const float*)d_in[7];
    const float* Wq    = (const float*)d_in[8];
    const float* bq    = (const float*)d_in[9];
    const float* Wk    = (const float*)d_in[10];
    const float* bk    = (const float*)d_in[11];
    const float* Wv    = (const float*)d_in[12];
    const float* bv    = (const float*)d_in[13];
    const float* Wih   = (const float*)d_in[14];
    const float* bih   = (const float*)d_in[15];
    const float* Whh   = (const float*)d_in[16];
    const float* bhh   = (const float*)d_in[17];
    const float* gs    = (const float*)d_in[18];
    const float* bs    = (const float*)d_in[19];
    const float* W1    = (const float*)d_in[20];
    const float* b1    = (const float*)d_in[21];
    const float* W2    = (const float*)d_in[22];
    const float* b2    = (const float*)d_in[23];
    const float* gm    = (const float*)d_in[24];
    const float* bm    = (const float*)d_in[25];

    float *pWpT, *pIn;
    cudaGetSymbolAddress((void**)&pWpT, g_WpT);
    cudaGetSymbolAddress((void**)&pIn,  g_inputs);

    const int slotsElems = BB*KSLOT*HH;
    const int attnElems  = BB*KSLOT*NN;
    const int writeSlots = (out_size >= slotsElems) ? 1 : 0;
    const int writeAttn  = (out_size >= slotsElems + attnElems) ? 1 : 0;
    float* outSlots = (float*)d_out;
    float* outAttn  = (float*)d_out + slotsElems;

    const int iterSmem = (int)sizeof(IterSmem);
    static int attrSet = 0;
    if (!attrSet) {
        cudaFuncSetAttribute(iter_kernel,
                             cudaFuncAttributeMaxDynamicSharedMemorySize, iterSmem);
        attrSet = 1;
    }

    // 1) transpose Wp + init slots
    prep_kernel<<<192, 256>>>(Wp, noise, smu, slsig);

    // 2) inputs = LN(X @ Wp^T + bp)
    gemm_ln<DIN><<<MTOT/128, 256>>>(patch, pWpT, bp, g_in, b_in, pIn);

    // 3) 3 slot-attention iterations
    for (int it = 0; it < NITER; it++) {
        int last = (it == NITER - 1);
        iter_kernel<<<BB, 1024, iterSmem>>>(Wq, bq, Wk, bk, Wv, bv,
                                            gs, bs, Wih, bih, Whh, bhh,
                                            W1, b1, W2, b2, gm, bm,
                                            outSlots, outAttn,
                                            last ? writeSlots : 0,
                                            last ? writeAttn  : 0);
    }
}